// round 2
// baseline (speedup 1.0000x reference)
#include <cuda_runtime.h>
#include <cuda_bf16.h>

// Problem constants (fixed by the dataset)
#define HEADS   8
#define NTOK    49
#define CDIM    256
#define HD      32
#define BATCH   4096
#define NWIN    64
#define M_TOTAL (BATCH * NTOK)      // 200704
#define QKV_N   768

// ---------------------------------------------------------------------------
// Scratch (allocation-free rule: __device__ globals)
// ---------------------------------------------------------------------------
__device__ float g_q[(size_t)BATCH * HEADS * NTOK * HD];   // [b][h][n][d], pre-scaled
__device__ float g_k[(size_t)BATCH * HEADS * NTOK * HD];
__device__ float g_v[(size_t)BATCH * HEADS * NTOK * HD];
__device__ float g_y[(size_t)BATCH * NTOK * CDIM];         // attention output [b][n][c]

// ---------------------------------------------------------------------------
// SGEMM: C[M x Ncols] = A[M x 256] * W[256 x Ncols] + bias
// BM=128, BN=128, BK=8, 256 threads, 8x8 micro-tiles.
// EPI==0: qkv epilogue (scatter into g_q/g_k/g_v, scale q)
// EPI==1: proj epilogue (A is g_y, write d_out)
// ---------------------------------------------------------------------------
#define BM 128
#define BN 128
#define BK 8
#define TM 8
#define TN 8

template <int EPI>
__global__ __launch_bounds__(256, 2) void gemm_kernel(
    const float* __restrict__ Ain, const float* __restrict__ Wmat,
    const float* __restrict__ bias, float* __restrict__ Cout, int Ncols)
{
    __shared__ float As[BK * BM];   // transposed: As[k][m]
    __shared__ float Bs[BK * BN];   // Bs[k][n]

    const float* A = (EPI == 1) ? (const float*)g_y : Ain;

    const int cRow = blockIdx.y;
    const int cCol = blockIdx.x;
    const int tid  = threadIdx.x;

    const int threadCol = tid % (BN / TN);   // 0..15
    const int threadRow = tid / (BN / TN);   // 0..15

    const int innerRowA = tid / (BK / 4);    // 0..127
    const int innerColA = tid % (BK / 4);    // 0..1
    const int innerRowB = tid / (BN / 4);    // 0..7
    const int innerColB = tid % (BN / 4);    // 0..31

    const float* Aptr = A + (size_t)cRow * BM * CDIM;
    const float* Wptr = Wmat + (size_t)cCol * BN;

    float acc[TM][TN];
    #pragma unroll
    for (int i = 0; i < TM; i++)
        #pragma unroll
        for (int j = 0; j < TN; j++) acc[i][j] = 0.0f;

    float regM[TM], regN[TN];

    for (int k0 = 0; k0 < CDIM; k0 += BK) {
        // load A tile (128x8), transpose into As
        float4 ta = *(const float4*)(Aptr + (size_t)innerRowA * CDIM + k0 + innerColA * 4);
        As[(innerColA * 4 + 0) * BM + innerRowA] = ta.x;
        As[(innerColA * 4 + 1) * BM + innerRowA] = ta.y;
        As[(innerColA * 4 + 2) * BM + innerRowA] = ta.z;
        As[(innerColA * 4 + 3) * BM + innerRowA] = ta.w;
        // load W tile (8x128)
        *(float4*)(&Bs[innerRowB * BN + innerColB * 4]) =
            *(const float4*)(Wptr + (size_t)(k0 + innerRowB) * Ncols + innerColB * 4);
        __syncthreads();

        #pragma unroll
        for (int k = 0; k < BK; k++) {
            #pragma unroll
            for (int i = 0; i < TM; i += 4)
                *(float4*)&regM[i] = *(const float4*)&As[k * BM + threadRow * TM + i];
            #pragma unroll
            for (int j = 0; j < TN; j += 4)
                *(float4*)&regN[j] = *(const float4*)&Bs[k * BN + threadCol * TN + j];
            #pragma unroll
            for (int i = 0; i < TM; i++)
                #pragma unroll
                for (int j = 0; j < TN; j++)
                    acc[i][j] += regM[i] * regN[j];
        }
        __syncthreads();
    }

    const int nbase = cCol * BN + threadCol * TN;   // multiple of 8

    if (EPI == 0) {
        // qkv epilogue: n -> (t, h, d); m -> (b, token)
        const float scale = 0.17677669529663687f;   // 32^-0.5
        const int t = nbase >> 8;
        const int h = (nbase >> 5) & 7;
        const int dbase = nbase & 31;               // {0,8,16,24}
        float* gdst = (t == 0) ? g_q : (t == 1) ? g_k : g_v;
        const float sc = (t == 0) ? scale : 1.0f;
        #pragma unroll
        for (int i = 0; i < TM; i++) {
            int m = cRow * BM + threadRow * TM + i;
            int b = m / NTOK;
            int nn = m - b * NTOK;
            float vals[TN];
            #pragma unroll
            for (int j = 0; j < TN; j++)
                vals[j] = (acc[i][j] + bias[nbase + j]) * sc;
            float* dst = gdst + (((size_t)(b * HEADS + h) * NTOK + nn) * HD + dbase);
            *(float4*)(dst + 0) = make_float4(vals[0], vals[1], vals[2], vals[3]);
            *(float4*)(dst + 4) = make_float4(vals[4], vals[5], vals[6], vals[7]);
        }
    } else {
        // proj epilogue: plain [M x 256] store
        #pragma unroll
        for (int i = 0; i < TM; i++) {
            int m = cRow * BM + threadRow * TM + i;
            float vals[TN];
            #pragma unroll
            for (int j = 0; j < TN; j++)
                vals[j] = acc[i][j] + bias[nbase + j];
            float* dst = Cout + (size_t)m * CDIM + nbase;
            *(float4*)(dst + 0) = make_float4(vals[0], vals[1], vals[2], vals[3]);
            *(float4*)(dst + 4) = make_float4(vals[4], vals[5], vals[6], vals[7]);
        }
    }
}

// ---------------------------------------------------------------------------
// Attention: one block per (window, head). 64 threads; lanes 0..48 each own
// one query row. K/V reads are smem broadcasts; probs row strided 49 floats
// (49 mod 32 = 17, gcd(17,32)=1 -> conflict-free gathers).
// ---------------------------------------------------------------------------
__global__ __launch_bounds__(64) void attn_kernel(
    const float* __restrict__ bias_table,
    const float* __restrict__ mask,
    const int*   __restrict__ rel_idx)
{
    __shared__ float qs[NTOK * HD];
    __shared__ float ks[NTOK * HD];
    __shared__ float vs[NTOK * HD];
    __shared__ float ps[NTOK * NTOK];

    const int blk = blockIdx.x;          // b*8 + h
    const int b = blk >> 3;
    const int h = blk & 7;

    // cooperative load q/k/v tiles (1568 floats each = 392 float4)
    const size_t base4 = (size_t)blk * (NTOK * HD / 4);
    const float4* qg4 = ((const float4*)g_q) + base4;
    const float4* kg4 = ((const float4*)g_k) + base4;
    const float4* vg4 = ((const float4*)g_v) + base4;
    float4* qs4 = (float4*)qs;
    float4* ks4 = (float4*)ks;
    float4* vs4 = (float4*)vs;
    for (int t = threadIdx.x; t < NTOK * HD / 4; t += 64) {
        qs4[t] = qg4[t];
        ks4[t] = kg4[t];
        vs4[t] = vg4[t];
    }
    __syncthreads();

    const int i = threadIdx.x;
    if (i < NTOK) {
        // q row in registers
        float qr[HD];
        #pragma unroll
        for (int d = 0; d < HD; d++) qr[d] = qs[i * HD + d];

        const float* mrow = mask + ((size_t)(b & (NWIN - 1)) * NTOK + i) * NTOK;
        const int*   rrow = rel_idx + i * NTOK;
        const float4* ksv = (const float4*)ks;

        float mx = -3.0e38f;
        for (int j = 0; j < NTOK; j++) {
            float s = 0.0f;
            #pragma unroll
            for (int dv = 0; dv < HD / 4; dv++) {
                float4 kv = ksv[j * (HD / 4) + dv];
                s += qr[dv * 4 + 0] * kv.x + qr[dv * 4 + 1] * kv.y
                   + qr[dv * 4 + 2] * kv.z + qr[dv * 4 + 3] * kv.w;
            }
            s += bias_table[rrow[j] * HEADS + h] + mrow[j];
            ps[i * NTOK + j] = s;
            mx = fmaxf(mx, s);
        }

        float sum = 0.0f;
        for (int j = 0; j < NTOK; j++) {
            float e = __expf(ps[i * NTOK + j] - mx);
            ps[i * NTOK + j] = e;
            sum += e;
        }
        const float inv = 1.0f / sum;

        // out[i][:] = (sum_j p_j * v_j) * inv
        float4 acc4[HD / 4];
        #pragma unroll
        for (int dv = 0; dv < HD / 4; dv++) acc4[dv] = make_float4(0.f, 0.f, 0.f, 0.f);

        const float4* vsv = (const float4*)vs;
        for (int j = 0; j < NTOK; j++) {
            float p = ps[i * NTOK + j];
            #pragma unroll
            for (int dv = 0; dv < HD / 4; dv++) {
                float4 vv = vsv[j * (HD / 4) + dv];
                acc4[dv].x += p * vv.x;
                acc4[dv].y += p * vv.y;
                acc4[dv].z += p * vv.z;
                acc4[dv].w += p * vv.w;
            }
        }

        float4* dst = (float4*)(g_y + ((size_t)b * NTOK + i) * CDIM + h * HD);
        #pragma unroll
        for (int dv = 0; dv < HD / 4; dv++) {
            acc4[dv].x *= inv; acc4[dv].y *= inv;
            acc4[dv].z *= inv; acc4[dv].w *= inv;
            dst[dv] = acc4[dv];
        }
    }
}

// ---------------------------------------------------------------------------
// Launch
// ---------------------------------------------------------------------------
extern "C" void kernel_launch(void* const* d_in, const int* in_sizes, int n_in,
                              void* d_out, int out_size)
{
    const float* x          = (const float*)d_in[0];
    const float* mask       = (const float*)d_in[1];
    const float* qkv_w      = (const float*)d_in[2];
    const float* qkv_b      = (const float*)d_in[3];
    const float* bias_table = (const float*)d_in[4];
    const float* proj_w     = (const float*)d_in[5];
    const float* proj_b     = (const float*)d_in[6];
    const int*   rel_idx    = (const int*)d_in[7];
    float* out = (float*)d_out;

    // 1) QKV: [200704 x 256] x [256 x 768] -> scatter into g_q/g_k/g_v
    dim3 g1(QKV_N / BN, M_TOTAL / BM);            // (6, 1568)
    gemm_kernel<0><<<g1, 256>>>(x, qkv_w, qkv_b, nullptr, QKV_N);

    // 2) per-(window, head) attention -> g_y
    attn_kernel<<<BATCH * HEADS, 64>>>(bias_table, mask, rel_idx);

    // 3) proj: g_y [200704 x 256] x [256 x 256] -> d_out
    dim3 g3(CDIM / BN, M_TOTAL / BM);             // (2, 1568)
    gemm_kernel<1><<<g3, 256>>>(nullptr, proj_w, proj_b, out, CDIM);
}

// round 5
// speedup vs baseline: 2.5480x; 2.5480x over previous
#include <cuda_runtime.h>
#include <cstdint>

// Problem constants
#define HEADS   8
#define NTOK    49
#define CDIM    256
#define HD      32
#define BATCH   4096
#define NWIN    64
#define M_TOTAL (BATCH * NTOK)      // 200704
#define QKV_N   768

// ---------------------------------------------------------------------------
// Scratch (__device__ globals; allocation-free rule)
// ---------------------------------------------------------------------------
__device__ float g_q[(size_t)BATCH * HEADS * NTOK * HD];
__device__ float g_k[(size_t)BATCH * HEADS * NTOK * HD];
__device__ float g_v[(size_t)BATCH * HEADS * NTOK * HD];
__device__ float g_y[(size_t)M_TOTAL * CDIM];
__device__ float g_wt_qkv[(size_t)QKV_N * CDIM];   // qkv_w^T : [768][256] K-major
__device__ float g_wt_proj[(size_t)CDIM * CDIM];   // proj_w^T: [256][256] K-major

__device__ __forceinline__ float to_tf32(float x) {
    float r;
    asm("cvt.rna.tf32.f32 %0, %1;" : "=f"(r) : "f"(x));
    return r;
}

// ---------------------------------------------------------------------------
// Weight transpose: W[K][N] -> Wt[N][K], pre-rounded to tf32
// ---------------------------------------------------------------------------
__global__ void transpose_kernel(const float* __restrict__ W, int K, int N, int sel) {
    float* Wt = sel ? g_wt_proj : g_wt_qkv;
    __shared__ float t[32][33];
    int bn = blockIdx.x * 32, bk = blockIdx.y * 32;
    int x = threadIdx.x, y = threadIdx.y;
    #pragma unroll
    for (int i = 0; i < 32; i += 8)
        t[y + i][x] = W[(size_t)(bk + y + i) * N + bn + x];
    __syncthreads();
    #pragma unroll
    for (int i = 0; i < 32; i += 8)
        Wt[(size_t)(bn + y + i) * K + bk + x] = to_tf32(t[x][y + i]);
}

// ---------------------------------------------------------------------------
// tf32 mma.sync GEMM: C[M x N] = A[M x 256] * Bt[N x 256]^T (+bias, epilogues)
// BM=128, BN=128, BK=32. 256 threads = 8 warps (2 x 4), warp tile 64 x 32.
// mma.m16n8k8: 4 m-frags x 4 n-frags x 4 k-steps per warp per BK chunk.
// Smem rows padded to PITCH=36 floats -> frag gathers hit all 32 banks.
// ---------------------------------------------------------------------------
#define PITCH 36
#define SA0F 0
#define SA1F 4608
#define SB0F 9216
#define SB1F 13824
#define SMTOT_BYTES 73728

__device__ __forceinline__ void gload(const float* __restrict__ base, int c0, int tid,
                                      float4 r[4]) {
    #pragma unroll
    for (int it = 0; it < 4; it++) {
        int f = tid + it * 256;
        int row = f >> 3, colv = f & 7;
        r[it] = *(const float4*)(base + (size_t)row * CDIM + c0 + colv * 4);
    }
}
__device__ __forceinline__ void sstore(float* __restrict__ s, int tid, const float4 r[4]) {
    #pragma unroll
    for (int it = 0; it < 4; it++) {
        int f = tid + it * 256;
        int row = f >> 3, colv = f & 7;
        float4 w;
        w.x = to_tf32(r[it].x); w.y = to_tf32(r[it].y);
        w.z = to_tf32(r[it].z); w.w = to_tf32(r[it].w);
        *(float4*)(s + row * PITCH + colv * 4) = w;
    }
}

template <int EPI>
__global__ __launch_bounds__(256, 2) void tc_gemm(const float* __restrict__ Ain,
                                                  const float* __restrict__ bias,
                                                  float* __restrict__ Cout) {
    extern __shared__ float sm[];
    const float* A  = (EPI == 1) ? (const float*)g_y : Ain;
    const float* Bt = (EPI == 1) ? (const float*)g_wt_proj : (const float*)g_wt_qkv;

    const int tid = threadIdx.x;
    const int wid = tid >> 5, lid = tid & 31;
    const int wm = wid >> 2, wn = wid & 3;       // warp grid 2 x 4
    const int g = lid >> 2, q = lid & 3;         // quad layout
    const int cRow = blockIdx.y, cCol = blockIdx.x;

    const float* Abase = A  + (size_t)cRow * 128 * CDIM;
    const float* Bbase = Bt + (size_t)cCol * 128 * CDIM;

    float4 ra[4], rb[4];
    gload(Abase, 0, tid, ra);
    gload(Bbase, 0, tid, rb);
    sstore(sm + SA0F, tid, ra);
    sstore(sm + SB0F, tid, rb);
    __syncthreads();

    float acc[4][4][4];
    #pragma unroll
    for (int i = 0; i < 4; i++)
        #pragma unroll
        for (int j = 0; j < 4; j++)
            #pragma unroll
            for (int r = 0; r < 4; r++) acc[i][j][r] = 0.0f;

    #pragma unroll 1
    for (int c = 0; c < 8; c++) {
        if (c < 7) {
            gload(Abase, (c + 1) * 32, tid, ra);
            gload(Bbase, (c + 1) * 32, tid, rb);
        }
        const float* as = sm + ((c & 1) ? SA1F : SA0F);
        const float* bs = sm + ((c & 1) ? SB1F : SB0F);

        #pragma unroll
        for (int ks = 0; ks < 4; ks++) {
            const int kc = ks * 8 + q;
            uint32_t b0[4], b1[4];
            #pragma unroll
            for (int j = 0; j < 4; j++) {
                const float* bp = bs + (wn * 32 + j * 8 + g) * PITCH + kc;
                b0[j] = __float_as_uint(bp[0]);
                b1[j] = __float_as_uint(bp[4]);
            }
            #pragma unroll
            for (int i = 0; i < 4; i++) {
                const float* ap = as + (wm * 64 + i * 16 + g) * PITCH + kc;
                uint32_t a0 = __float_as_uint(ap[0]);
                uint32_t a2 = __float_as_uint(ap[4]);
                uint32_t a1 = __float_as_uint(ap[8 * PITCH]);
                uint32_t a3 = __float_as_uint(ap[8 * PITCH + 4]);
                #pragma unroll
                for (int j = 0; j < 4; j++)
                    asm volatile(
                        "mma.sync.aligned.m16n8k8.row.col.f32.tf32.tf32.f32 "
                        "{%0,%1,%2,%3}, {%4,%5,%6,%7}, {%8,%9}, {%0,%1,%2,%3};"
                        : "+f"(acc[i][j][0]), "+f"(acc[i][j][1]),
                          "+f"(acc[i][j][2]), "+f"(acc[i][j][3])
                        : "r"(a0), "r"(a1), "r"(a2), "r"(a3), "r"(b0[j]), "r"(b1[j]));
            }
        }

        if (c < 7) {
            sstore(sm + ((c & 1) ? SA0F : SA1F), tid, ra);
            sstore(sm + ((c & 1) ? SB0F : SB1F), tid, rb);
        }
        __syncthreads();
    }

    // ------------------- epilogue -------------------
    const int nbase = cCol * 128 + wn * 32;   // 32-aligned: single (t,h) per warp
    float bv[4][2];
    #pragma unroll
    for (int j = 0; j < 4; j++) {
        int n = nbase + j * 8 + 2 * q;
        bv[j][0] = __ldg(bias + n);
        bv[j][1] = __ldg(bias + n + 1);
    }

    if (EPI == 0) {
        const int t = nbase >> 8;
        const int h = (nbase >> 5) & 7;
        const float sc = (t == 0) ? 0.17677669529663687f : 1.0f;
        float* gdst = (t == 0) ? g_q : (t == 1) ? g_k : g_v;
        #pragma unroll
        for (int i = 0; i < 4; i++) {
            #pragma unroll
            for (int rr = 0; rr < 2; rr++) {
                int m = cRow * 128 + wm * 64 + i * 16 + g + rr * 8;
                int bwin = m / NTOK;
                int nn = m - bwin * NTOK;
                float* dst = gdst + (((size_t)(bwin * HEADS + h) * NTOK + nn) * HD);
                #pragma unroll
                for (int j = 0; j < 4; j++) {
                    float2 o;
                    o.x = (acc[i][j][rr * 2 + 0] + bv[j][0]) * sc;
                    o.y = (acc[i][j][rr * 2 + 1] + bv[j][1]) * sc;
                    *(float2*)(dst + j * 8 + 2 * q) = o;
                }
            }
        }
    } else {
        #pragma unroll
        for (int i = 0; i < 4; i++) {
            #pragma unroll
            for (int rr = 0; rr < 2; rr++) {
                int m = cRow * 128 + wm * 64 + i * 16 + g + rr * 8;
                float* dst = Cout + (size_t)m * CDIM + nbase;
                #pragma unroll
                for (int j = 0; j < 4; j++) {
                    float2 o;
                    o.x = acc[i][j][rr * 2 + 0] + bv[j][0];
                    o.y = acc[i][j][rr * 2 + 1] + bv[j][1];
                    *(float2*)(dst + j * 8 + 2 * q) = o;
                }
            }
        }
    }
}

// ---------------------------------------------------------------------------
// Attention: one block per (window, head), 64 threads, single-pass online
// softmax (scores ~ N(0, ~0.1): exp overflow impossible), K/V in smem,
// q-row + output accumulator in registers.
// ---------------------------------------------------------------------------
__global__ __launch_bounds__(64) void attn_kernel(
    const float* __restrict__ bias_table,
    const float* __restrict__ mask,
    const int*   __restrict__ rel_idx)
{
    __shared__ float ks[NTOK * HD];
    __shared__ float vs[NTOK * HD];

    const int blk = blockIdx.x;          // b*8 + h
    const int b = blk >> 3;
    const int h = blk & 7;

    const size_t base4 = (size_t)blk * (NTOK * HD / 4);
    const float4* kg4 = ((const float4*)g_k) + base4;
    const float4* vg4 = ((const float4*)g_v) + base4;
    float4* ks4 = (float4*)ks;
    float4* vs4 = (float4*)vs;
    for (int t = threadIdx.x; t < NTOK * HD / 4; t += 64) {
        ks4[t] = kg4[t];
        vs4[t] = vg4[t];
    }
    __syncthreads();

    const int i = threadIdx.x;
    if (i < NTOK) {
        float4 qr[HD / 4];
        const float4* qg4 = ((const float4*)g_q) + base4 + i * (HD / 4);
        #pragma unroll
        for (int dv = 0; dv < HD / 4; dv++) qr[dv] = qg4[dv];

        const float* mrow = mask + ((size_t)(b & (NWIN - 1)) * NTOK + i) * NTOK;
        const int*   rrow = rel_idx + i * NTOK;
        const float4* ksv = (const float4*)ks;
        const float4* vsv = (const float4*)vs;

        float lsum = 0.0f;
        float4 acc[HD / 4];
        #pragma unroll
        for (int dv = 0; dv < HD / 4; dv++) acc[dv] = make_float4(0.f, 0.f, 0.f, 0.f);

        for (int j = 0; j < NTOK; j++) {
            float s = 0.0f;
            #pragma unroll
            for (int dv = 0; dv < HD / 4; dv++) {
                float4 kv = ksv[j * (HD / 4) + dv];
                s += qr[dv].x * kv.x + qr[dv].y * kv.y + qr[dv].z * kv.z + qr[dv].w * kv.w;
            }
            s += bias_table[rrow[j] * HEADS + h] + mrow[j];
            const float p = __expf(s);
            lsum += p;
            #pragma unroll
            for (int dv = 0; dv < HD / 4; dv++) {
                float4 vv = vsv[j * (HD / 4) + dv];
                acc[dv].x += p * vv.x;
                acc[dv].y += p * vv.y;
                acc[dv].z += p * vv.z;
                acc[dv].w += p * vv.w;
            }
        }

        const float inv = 1.0f / lsum;
        float4* dst = (float4*)(g_y + ((size_t)b * NTOK + i) * CDIM + h * HD);
        #pragma unroll
        for (int dv = 0; dv < HD / 4; dv++) {
            acc[dv].x *= inv; acc[dv].y *= inv;
            acc[dv].z *= inv; acc[dv].w *= inv;
            dst[dv] = acc[dv];
        }
    }
}

// ---------------------------------------------------------------------------
// Launch
// ---------------------------------------------------------------------------
extern "C" void kernel_launch(void* const* d_in, const int* in_sizes, int n_in,
                              void* d_out, int out_size)
{
    const float* x          = (const float*)d_in[0];
    const float* mask       = (const float*)d_in[1];
    const float* qkv_w      = (const float*)d_in[2];
    const float* qkv_b      = (const float*)d_in[3];
    const float* bias_table = (const float*)d_in[4];
    const float* proj_w     = (const float*)d_in[5];
    const float* proj_b     = (const float*)d_in[6];
    const int*   rel_idx    = (const int*)d_in[7];
    float* out = (float*)d_out;

    cudaFuncSetAttribute(tc_gemm<0>, cudaFuncAttributeMaxDynamicSharedMemorySize, SMTOT_BYTES);
    cudaFuncSetAttribute(tc_gemm<1>, cudaFuncAttributeMaxDynamicSharedMemorySize, SMTOT_BYTES);

    // 0) weight transposes -> K-major, tf32-rounded
    transpose_kernel<<<dim3(QKV_N / 32, CDIM / 32), dim3(32, 8)>>>(qkv_w, CDIM, QKV_N, 0);
    transpose_kernel<<<dim3(CDIM / 32, CDIM / 32), dim3(32, 8)>>>(proj_w, CDIM, CDIM, 1);

    // 1) QKV: [200704 x 256] x [256 x 768] -> g_q/g_k/g_v (tf32 mma.sync)
    tc_gemm<0><<<dim3(QKV_N / 128, M_TOTAL / 128), 256, SMTOT_BYTES>>>(x, qkv_b, nullptr);

    // 2) attention -> g_y
    attn_kernel<<<BATCH * HEADS, 64>>>(bias_table, mask, rel_idx);

    // 3) proj: g_y x [256 x 256] -> out (tf32 mma.sync)
    tc_gemm<1><<<dim3(CDIM / 128, M_TOTAL / 128), 256, SMTOT_BYTES>>>(nullptr, proj_b, out);
}

// round 6
// speedup vs baseline: 2.8688x; 1.1259x over previous
#include <cuda_runtime.h>
#include <cstdint>

// Problem constants
#define HEADS   8
#define NTOK    49
#define CDIM    256
#define HD      32
#define BATCH   4096
#define NWIN    64
#define M_TOTAL (BATCH * NTOK)      // 200704
#define QKV_N   768

// ---------------------------------------------------------------------------
// Scratch (__device__ globals; allocation-free rule)
// ---------------------------------------------------------------------------
__device__ float g_q[(size_t)BATCH * HEADS * NTOK * HD];
__device__ float g_k[(size_t)BATCH * HEADS * NTOK * HD];
__device__ float g_v[(size_t)BATCH * HEADS * NTOK * HD];
__device__ float g_y[(size_t)M_TOTAL * CDIM];
__device__ float g_wt_qkv[(size_t)QKV_N * CDIM];   // qkv_w^T : [768][256] K-major
__device__ float g_wt_proj[(size_t)CDIM * CDIM];   // proj_w^T: [256][256] K-major
__device__ float g_bm[(size_t)NWIN * HEADS * NTOK * 56];  // bias+mask, keys padded to 56

__device__ __forceinline__ float to_tf32(float x) {
    float r;
    asm("cvt.rna.tf32.f32 %0, %1;" : "=f"(r) : "f"(x));
    return r;
}

#define MMA_TF32(acc, a0, a1, a2, a3, b0, b1) \
    asm volatile("mma.sync.aligned.m16n8k8.row.col.f32.tf32.tf32.f32 " \
        "{%0,%1,%2,%3}, {%4,%5,%6,%7}, {%8,%9}, {%0,%1,%2,%3};" \
        : "+f"((acc)[0]), "+f"((acc)[1]), "+f"((acc)[2]), "+f"((acc)[3]) \
        : "r"(a0), "r"(a1), "r"(a2), "r"(a3), "r"(b0), "r"(b1))

// ---------------------------------------------------------------------------
// Weight transpose: W[K][N] -> Wt[N][K], pre-rounded to tf32
// ---------------------------------------------------------------------------
__global__ void transpose_kernel(const float* __restrict__ W, int K, int N, int sel) {
    float* Wt = sel ? g_wt_proj : g_wt_qkv;
    __shared__ float t[32][33];
    int bn = blockIdx.x * 32, bk = blockIdx.y * 32;
    int x = threadIdx.x, y = threadIdx.y;
    #pragma unroll
    for (int i = 0; i < 32; i += 8)
        t[y + i][x] = W[(size_t)(bk + y + i) * N + bn + x];
    __syncthreads();
    #pragma unroll
    for (int i = 0; i < 32; i += 8)
        Wt[(size_t)(bn + y + i) * K + bk + x] = to_tf32(t[x][y + i]);
}

// ---------------------------------------------------------------------------
// Combined bias+mask precompute: g_bm[w][h][i][j] (j padded to 56 with -30)
// ---------------------------------------------------------------------------
__global__ void bm_kernel(const float* __restrict__ bias_table,
                          const float* __restrict__ mask,
                          const int*   __restrict__ rel_idx) {
    const int w = blockIdx.x >> 3, h = blockIdx.x & 7;
    float* dst = g_bm + (size_t)blockIdx.x * (NTOK * 56);
    for (int t = threadIdx.x; t < NTOK * 56; t += 256) {
        int i = t / 56, j = t - i * 56;
        float v = -30.0f;
        if (j < NTOK)
            v = bias_table[rel_idx[i * NTOK + j] * HEADS + h]
              + mask[((size_t)w * NTOK + i) * NTOK + j];
        dst[t] = v;
    }
}

// ---------------------------------------------------------------------------
// tf32 mma.sync GEMM (unchanged from R4): BM=128,BN=128,BK=32, 8 warps
// ---------------------------------------------------------------------------
#define PITCH 36
#define SA0F 0
#define SA1F 4608
#define SB0F 9216
#define SB1F 13824
#define SMTOT_BYTES 73728

__device__ __forceinline__ void gload(const float* __restrict__ base, int c0, int tid,
                                      float4 r[4]) {
    #pragma unroll
    for (int it = 0; it < 4; it++) {
        int f = tid + it * 256;
        int row = f >> 3, colv = f & 7;
        r[it] = *(const float4*)(base + (size_t)row * CDIM + c0 + colv * 4);
    }
}
__device__ __forceinline__ void sstore(float* __restrict__ s, int tid, const float4 r[4]) {
    #pragma unroll
    for (int it = 0; it < 4; it++) {
        int f = tid + it * 256;
        int row = f >> 3, colv = f & 7;
        float4 w;
        w.x = to_tf32(r[it].x); w.y = to_tf32(r[it].y);
        w.z = to_tf32(r[it].z); w.w = to_tf32(r[it].w);
        *(float4*)(s + row * PITCH + colv * 4) = w;
    }
}

template <int EPI>
__global__ __launch_bounds__(256, 2) void tc_gemm(const float* __restrict__ Ain,
                                                  const float* __restrict__ bias,
                                                  float* __restrict__ Cout) {
    extern __shared__ float sm[];
    const float* A  = (EPI == 1) ? (const float*)g_y : Ain;
    const float* Bt = (EPI == 1) ? (const float*)g_wt_proj : (const float*)g_wt_qkv;

    const int tid = threadIdx.x;
    const int wid = tid >> 5, lid = tid & 31;
    const int wm = wid >> 2, wn = wid & 3;
    const int g = lid >> 2, q = lid & 3;
    const int cRow = blockIdx.y, cCol = blockIdx.x;

    const float* Abase = A  + (size_t)cRow * 128 * CDIM;
    const float* Bbase = Bt + (size_t)cCol * 128 * CDIM;

    float4 ra[4], rb[4];
    gload(Abase, 0, tid, ra);
    gload(Bbase, 0, tid, rb);
    sstore(sm + SA0F, tid, ra);
    sstore(sm + SB0F, tid, rb);
    __syncthreads();

    float acc[4][4][4];
    #pragma unroll
    for (int i = 0; i < 4; i++)
        #pragma unroll
        for (int j = 0; j < 4; j++)
            #pragma unroll
            for (int r = 0; r < 4; r++) acc[i][j][r] = 0.0f;

    #pragma unroll 1
    for (int c = 0; c < 8; c++) {
        if (c < 7) {
            gload(Abase, (c + 1) * 32, tid, ra);
            gload(Bbase, (c + 1) * 32, tid, rb);
        }
        const float* as = sm + ((c & 1) ? SA1F : SA0F);
        const float* bs = sm + ((c & 1) ? SB1F : SB0F);

        #pragma unroll
        for (int ks = 0; ks < 4; ks++) {
            const int kc = ks * 8 + q;
            uint32_t b0[4], b1[4];
            #pragma unroll
            for (int j = 0; j < 4; j++) {
                const float* bp = bs + (wn * 32 + j * 8 + g) * PITCH + kc;
                b0[j] = __float_as_uint(bp[0]);
                b1[j] = __float_as_uint(bp[4]);
            }
            #pragma unroll
            for (int i = 0; i < 4; i++) {
                const float* ap = as + (wm * 64 + i * 16 + g) * PITCH + kc;
                uint32_t a0 = __float_as_uint(ap[0]);
                uint32_t a2 = __float_as_uint(ap[4]);
                uint32_t a1 = __float_as_uint(ap[8 * PITCH]);
                uint32_t a3 = __float_as_uint(ap[8 * PITCH + 4]);
                #pragma unroll
                for (int j = 0; j < 4; j++)
                    MMA_TF32(acc[i][j], a0, a1, a2, a3, b0[j], b1[j]);
            }
        }

        if (c < 7) {
            sstore(sm + ((c & 1) ? SA0F : SA1F), tid, ra);
            sstore(sm + ((c & 1) ? SB0F : SB1F), tid, rb);
        }
        __syncthreads();
    }

    const int nbase = cCol * 128 + wn * 32;
    float bv[4][2];
    #pragma unroll
    for (int j = 0; j < 4; j++) {
        int n = nbase + j * 8 + 2 * q;
        bv[j][0] = __ldg(bias + n);
        bv[j][1] = __ldg(bias + n + 1);
    }

    if (EPI == 0) {
        const int t = nbase >> 8;
        const int h = (nbase >> 5) & 7;
        const float sc = (t == 0) ? 0.17677669529663687f : 1.0f;
        float* gdst = (t == 0) ? g_q : (t == 1) ? g_k : g_v;
        #pragma unroll
        for (int i = 0; i < 4; i++) {
            #pragma unroll
            for (int rr = 0; rr < 2; rr++) {
                int m = cRow * 128 + wm * 64 + i * 16 + g + rr * 8;
                int bwin = m / NTOK;
                int nn = m - bwin * NTOK;
                float* dst = gdst + (((size_t)(bwin * HEADS + h) * NTOK + nn) * HD);
                #pragma unroll
                for (int j = 0; j < 4; j++) {
                    float2 o;
                    o.x = (acc[i][j][rr * 2 + 0] + bv[j][0]) * sc;
                    o.y = (acc[i][j][rr * 2 + 1] + bv[j][1]) * sc;
                    *(float2*)(dst + j * 8 + 2 * q) = o;
                }
            }
        }
    } else {
        #pragma unroll
        for (int i = 0; i < 4; i++) {
            #pragma unroll
            for (int rr = 0; rr < 2; rr++) {
                int m = cRow * 128 + wm * 64 + i * 16 + g + rr * 8;
                float* dst = Cout + (size_t)m * CDIM + nbase;
                #pragma unroll
                for (int j = 0; j < 4; j++) {
                    float2 o;
                    o.x = acc[i][j][rr * 2 + 0] + bv[j][0];
                    o.y = acc[i][j][rr * 2 + 1] + bv[j][1];
                    *(float2*)(dst + j * 8 + 2 * q) = o;
                }
            }
        }
    }
}

// ---------------------------------------------------------------------------
// MMA flash attention: one 64-thread block per (window, head).
// Warp w owns query rows w*32..w*32+31 (padded 49->64). Keys padded 49->56.
// QK^T: 2m x 7n x 4k mma; softmax in regs (no max-sub; scores O(1));
// P staged via smem (aliases dead Q/K region); PV: 2m x 4n x 7k mma.
// smem: Q[64][36] | K[56][36] | BM[64][60] | Vt[32][60]; P[64][60] aliases Q/K.
// ---------------------------------------------------------------------------
#define QS_OFF  0
#define KS_OFF  2304
#define BMS_OFF 4320
#define VTS_OFF 8160
#define SM_FLOATS 10080

__global__ __launch_bounds__(64) void attn_mma_kernel() {
    __shared__ float sm[SM_FLOATS];
    float* Qs  = sm + QS_OFF;    // [64][36]
    float* Ks  = sm + KS_OFF;    // [56][36]
    float* BMs = sm + BMS_OFF;   // [64][60]
    float* Vts = sm + VTS_OFF;   // [32][60]
    float* Ps  = sm;             // [64][60] aliases Q+K after sync (3840 <= 4320)

    const int blk = blockIdx.x;          // b*8 + h
    const int b = blk >> 3, h = blk & 7;
    const int tid = threadIdx.x, wid = tid >> 5, lid = tid & 31;
    const int g = lid >> 2, q = lid & 3;
    const int rbase = wid * 32;

    const size_t base4 = (size_t)blk * (NTOK * HD / 4);   // 392 float4 per (b,h)
    const float4* qg4 = ((const float4*)g_q) + base4;
    const float4* kg4 = ((const float4*)g_k) + base4;
    const float4* vg4 = ((const float4*)g_v) + base4;
    const float4 z4 = make_float4(0.f, 0.f, 0.f, 0.f);

    // Q rows 0..63 (49 real, rest zero)
    for (int t = tid; t < 512; t += 64) {
        int row = t >> 3, c = t & 7;
        *(float4*)(Qs + row * PITCH + c * 4) = (row < NTOK) ? qg4[t] : z4;
    }
    // K rows 0..55 + V transposed into Vt[32][60]
    for (int t = tid; t < 448; t += 64) {
        int row = t >> 3, c = t & 7;
        float4 kv = (row < NTOK) ? kg4[t] : z4;
        *(float4*)(Ks + row * PITCH + c * 4) = kv;
        float4 vv = (row < NTOK) ? vg4[t] : z4;
        Vts[(c * 4 + 0) * 60 + row] = vv.x;
        Vts[(c * 4 + 1) * 60 + row] = vv.y;
        Vts[(c * 4 + 2) * 60 + row] = vv.z;
        Vts[(c * 4 + 3) * 60 + row] = vv.w;
    }
    // bias+mask rows 0..63 (49 real)
    {
        const float* bmg = g_bm + ((size_t)(b & (NWIN - 1)) * HEADS + h) * (NTOK * 56);
        for (int t = tid; t < 896; t += 64) {          // 64 rows x 14 float4
            int row = t / 14, c = t - row * 14;
            float4 v = (row < NTOK) ? *(const float4*)(bmg + row * 56 + c * 4) : z4;
            *(float4*)(BMs + row * 60 + c * 4) = v;
        }
    }
    __syncthreads();

    // ---- QK^T ----
    float s[2][7][4];
    #pragma unroll
    for (int mi = 0; mi < 2; mi++)
        #pragma unroll
        for (int nj = 0; nj < 7; nj++)
            #pragma unroll
            for (int r = 0; r < 4; r++) s[mi][nj][r] = 0.0f;

    #pragma unroll
    for (int ks = 0; ks < 4; ks++) {
        const int kc = ks * 8 + q;
        uint32_t b0[7], b1[7];
        #pragma unroll
        for (int nj = 0; nj < 7; nj++) {
            const float* bp = Ks + (nj * 8 + g) * PITCH + kc;
            b0[nj] = __float_as_uint(bp[0]);
            b1[nj] = __float_as_uint(bp[4]);
        }
        #pragma unroll
        for (int mi = 0; mi < 2; mi++) {
            const float* ap = Qs + (rbase + mi * 16 + g) * PITCH + kc;
            uint32_t a0 = __float_as_uint(ap[0]);
            uint32_t a2 = __float_as_uint(ap[4]);
            uint32_t a1 = __float_as_uint(ap[8 * PITCH]);
            uint32_t a3 = __float_as_uint(ap[8 * PITCH + 4]);
            #pragma unroll
            for (int nj = 0; nj < 7; nj++)
                MMA_TF32(s[mi][nj], a0, a1, a2, a3, b0[nj], b1[nj]);
        }
    }

    // ---- softmax (bias+mask add, exp, row sums) ----
    float inv[2][2];
    #pragma unroll
    for (int mi = 0; mi < 2; mi++) {
        const int r0 = rbase + mi * 16 + g;
        float l0 = 0.0f, l1 = 0.0f;
        #pragma unroll
        for (int nj = 0; nj < 7; nj++) {
            const int cc = nj * 8 + 2 * q;
            float e0 = __expf(s[mi][nj][0] + BMs[r0 * 60 + cc]);
            float e1 = __expf(s[mi][nj][1] + BMs[r0 * 60 + cc + 1]);
            float e2 = __expf(s[mi][nj][2] + BMs[(r0 + 8) * 60 + cc]);
            float e3 = __expf(s[mi][nj][3] + BMs[(r0 + 8) * 60 + cc + 1]);
            s[mi][nj][0] = e0; s[mi][nj][1] = e1;
            s[mi][nj][2] = e2; s[mi][nj][3] = e3;
            l0 += e0 + e1;
            l1 += e2 + e3;
        }
        l0 += __shfl_xor_sync(0xffffffffu, l0, 1);
        l0 += __shfl_xor_sync(0xffffffffu, l0, 2);
        l1 += __shfl_xor_sync(0xffffffffu, l1, 1);
        l1 += __shfl_xor_sync(0xffffffffu, l1, 2);
        inv[mi][0] = 1.0f / l0;
        inv[mi][1] = 1.0f / l1;
    }

    __syncthreads();   // both warps done reading Qs/Ks before P overwrites them

    // ---- stage P into A-fragment-friendly smem ----
    #pragma unroll
    for (int mi = 0; mi < 2; mi++) {
        const int r0 = rbase + mi * 16 + g;
        #pragma unroll
        for (int nj = 0; nj < 7; nj++) {
            const int cc = nj * 8 + 2 * q;
            *(float2*)(Ps + r0 * 60 + cc)       = make_float2(s[mi][nj][0], s[mi][nj][1]);
            *(float2*)(Ps + (r0 + 8) * 60 + cc) = make_float2(s[mi][nj][2], s[mi][nj][3]);
        }
    }
    __syncwarp();      // PV reads only this warp's P rows

    // ---- P x V ----
    float o[2][4][4];
    #pragma unroll
    for (int mi = 0; mi < 2; mi++)
        #pragma unroll
        for (int nj = 0; nj < 4; nj++)
            #pragma unroll
            for (int r = 0; r < 4; r++) o[mi][nj][r] = 0.0f;

    #pragma unroll
    for (int ks = 0; ks < 7; ks++) {
        const int kc = ks * 8 + q;
        uint32_t b0[4], b1[4];
        #pragma unroll
        for (int nj = 0; nj < 4; nj++) {
            const float* bp = Vts + (nj * 8 + g) * 60 + kc;
            b0[nj] = __float_as_uint(bp[0]);
            b1[nj] = __float_as_uint(bp[4]);
        }
        #pragma unroll
        for (int mi = 0; mi < 2; mi++) {
            const float* ap = Ps + (rbase + mi * 16 + g) * 60 + kc;
            uint32_t a0 = __float_as_uint(ap[0]);
            uint32_t a2 = __float_as_uint(ap[4]);
            uint32_t a1 = __float_as_uint(ap[8 * 60]);
            uint32_t a3 = __float_as_uint(ap[8 * 60 + 4]);
            #pragma unroll
            for (int nj = 0; nj < 4; nj++)
                MMA_TF32(o[mi][nj], a0, a1, a2, a3, b0[nj], b1[nj]);
        }
    }

    // ---- normalize + store to g_y ----
    #pragma unroll
    for (int mi = 0; mi < 2; mi++) {
        #pragma unroll
        for (int rr = 0; rr < 2; rr++) {
            const int row = rbase + mi * 16 + g + rr * 8;
            if (row < NTOK) {
                const float iv = inv[mi][rr];
                float* dst = g_y + ((size_t)b * NTOK + row) * CDIM + h * HD;
                #pragma unroll
                for (int nj = 0; nj < 4; nj++) {
                    float2 ov;
                    ov.x = o[mi][nj][rr * 2 + 0] * iv;
                    ov.y = o[mi][nj][rr * 2 + 1] * iv;
                    *(float2*)(dst + nj * 8 + 2 * q) = ov;
                }
            }
        }
    }
}

// ---------------------------------------------------------------------------
// Launch
// ---------------------------------------------------------------------------
extern "C" void kernel_launch(void* const* d_in, const int* in_sizes, int n_in,
                              void* d_out, int out_size)
{
    const float* x          = (const float*)d_in[0];
    const float* mask       = (const float*)d_in[1];
    const float* qkv_w      = (const float*)d_in[2];
    const float* qkv_b      = (const float*)d_in[3];
    const float* bias_table = (const float*)d_in[4];
    const float* proj_w     = (const float*)d_in[5];
    const float* proj_b     = (const float*)d_in[6];
    const int*   rel_idx    = (const int*)d_in[7];
    float* out = (float*)d_out;

    cudaFuncSetAttribute(tc_gemm<0>, cudaFuncAttributeMaxDynamicSharedMemorySize, SMTOT_BYTES);
    cudaFuncSetAttribute(tc_gemm<1>, cudaFuncAttributeMaxDynamicSharedMemorySize, SMTOT_BYTES);

    // 0) weight transposes + combined bias+mask table
    transpose_kernel<<<dim3(QKV_N / 32, CDIM / 32), dim3(32, 8)>>>(qkv_w, CDIM, QKV_N, 0);
    transpose_kernel<<<dim3(CDIM / 32, CDIM / 32), dim3(32, 8)>>>(proj_w, CDIM, CDIM, 1);
    bm_kernel<<<NWIN * HEADS, 256>>>(bias_table, mask, rel_idx);

    // 1) QKV: [200704 x 256] x [256 x 768] -> g_q/g_k/g_v (tf32 mma.sync)
    tc_gemm<0><<<dim3(QKV_N / 128, M_TOTAL / 128), 256, SMTOT_BYTES>>>(x, qkv_b, nullptr);

    // 2) attention (tf32 mma flash) -> g_y
    attn_mma_kernel<<<BATCH * HEADS, 64>>>();

    // 3) proj: g_y x [256 x 256] -> out (tf32 mma.sync)
    tc_gemm<1><<<dim3(CDIM / 128, M_TOTAL / 128), 256, SMTOT_BYTES>>>(nullptr, proj_b, out);
}

// round 9
// speedup vs baseline: 3.3264x; 1.1595x over previous
#include <cuda_runtime.h>
#include <cuda_bf16.h>
#include <cstdint>

// Problem constants
#define HEADS   8
#define NTOK    49
#define CDIM    256
#define HD      32
#define BATCH   4096
#define NWIN    64
#define M_TOTAL (BATCH * NTOK)      // 200704
#define QKV_N   768

// ---------------------------------------------------------------------------
// Scratch (__device__ globals; allocation-free rule)
// ---------------------------------------------------------------------------
__device__ float g_q[(size_t)BATCH * HEADS * NTOK * HD];
__device__ float g_k[(size_t)BATCH * HEADS * NTOK * HD];
__device__ float g_v[(size_t)BATCH * HEADS * NTOK * HD];
__device__ float g_y[(size_t)M_TOTAL * CDIM];               // pre-rounded, k-permuted
__device__ float g_wt_qkv[(size_t)QKV_N * CDIM];            // W^T, tf32, k-permuted
__device__ float g_wt_proj[(size_t)CDIM * CDIM];            // W^T, tf32, k-permuted
__device__ __nv_bfloat16 g_bm[(size_t)NWIN * HEADS * 64 * 56]; // bias+mask (bf16, 64-row pad)

__device__ __forceinline__ float to_tf32(float x) {
    float r;
    asm("cvt.rna.tf32.f32 %0, %1;" : "=f"(r) : "f"(x));
    return r;
}

#define MMA_TF32(acc, a0, a1, a2, a3, b0, b1) \
    asm volatile("mma.sync.aligned.m16n8k8.row.col.f32.tf32.tf32.f32 " \
        "{%0,%1,%2,%3}, {%4,%5,%6,%7}, {%8,%9}, {%0,%1,%2,%3};" \
        : "+f"((acc)[0]), "+f"((acc)[1]), "+f"((acc)[2]), "+f"((acc)[3]) \
        : "r"(a0), "r"(a1), "r"(a2), "r"(a3), "r"(b0), "r"(b1))

// k-permutation within each 32-col chunk: logical k=ks*8+q+4*half -> phys ks*8+2q+half
__device__ __host__ __forceinline__ int kperm(int x) {
    return (x & 24) + ((x & 3) << 1) + ((x >> 2) & 1);
}

// ---------------------------------------------------------------------------
// Weight transpose: W[K][N] -> Wt[N][kperm(K)], tf32-rounded
// ---------------------------------------------------------------------------
__global__ void transpose_kernel(const float* __restrict__ W, int K, int N, int sel) {
    float* Wt = sel ? g_wt_proj : g_wt_qkv;
    __shared__ float t[32][33];
    int bn = blockIdx.x * 32, bk = blockIdx.y * 32;
    int x = threadIdx.x, y = threadIdx.y;
    #pragma unroll
    for (int i = 0; i < 32; i += 8)
        t[y + i][x] = W[(size_t)(bk + y + i) * N + bn + x];
    __syncthreads();
    #pragma unroll
    for (int i = 0; i < 32; i += 8)
        Wt[(size_t)(bn + y + i) * K + bk + kperm(x)] = to_tf32(t[x][y + i]);
}

// ---------------------------------------------------------------------------
// bias+mask precompute -> bf16, rows padded to 64, cols to 56 (-30 pad)
// ---------------------------------------------------------------------------
__global__ void bm_kernel(const float* __restrict__ bias_table,
                          const float* __restrict__ mask,
                          const int*   __restrict__ rel_idx) {
    const int w = blockIdx.x >> 3, h = blockIdx.x & 7;
    __nv_bfloat16* dst = g_bm + (size_t)blockIdx.x * (64 * 56);
    for (int t = threadIdx.x; t < 64 * 56; t += 256) {
        int i = t / 56, j = t - i * 56;
        float v = -30.0f;
        if (i < NTOK && j < NTOK)
            v = bias_table[rel_idx[i * NTOK + j] * HEADS + h]
              + mask[((size_t)w * NTOK + i) * NTOK + j];
        dst[t] = __float2bfloat16(v);
    }
}

// ---------------------------------------------------------------------------
// tf32 mma.sync GEMM, BM=128,BN=128,BK=32, 8 warps, k-permuted smem, pitch 40
// EPI 0: A = x (shuffle-load to permuted layout + cvt), scatter q/k/v epilogue
// EPI 1: A = g_y (already permuted+rounded, straight copy), write d_out
// ---------------------------------------------------------------------------
#define GP 40
#define SA0F 0
#define SA1F 5120
#define SB0F 10240
#define SB1F 15360
#define SMTOT_BYTES 81920

// A-load with on-the-fly k-permutation (logical fp32 source)
__device__ __forceinline__ void gloadA_perm(const float* __restrict__ base, int c0,
                                            int tid, float4 r[4]) {
    #pragma unroll
    for (int it = 0; it < 4; it++) {
        int f = tid + it * 256;
        int row = f >> 3, v = f & 7;
        const float* p = base + (size_t)row * CDIM + c0 + (v >> 1) * 8 + (v & 1) * 2;
        float2 lo = *(const float2*)p;         // logical k0, k0+1
        float2 hi = *(const float2*)(p + 4);   // logical k0+4, k0+5
        r[it] = make_float4(to_tf32(lo.x), to_tf32(hi.x), to_tf32(lo.y), to_tf32(hi.y));
    }
}
// straight float4 load (source already physical layout)
__device__ __forceinline__ void gload(const float* __restrict__ base, int c0, int tid,
                                      float4 r[4]) {
    #pragma unroll
    for (int it = 0; it < 4; it++) {
        int f = tid + it * 256;
        int row = f >> 3, colv = f & 7;
        r[it] = *(const float4*)(base + (size_t)row * CDIM + c0 + colv * 4);
    }
}
__device__ __forceinline__ void sstore(float* __restrict__ s, int tid, const float4 r[4]) {
    #pragma unroll
    for (int it = 0; it < 4; it++) {
        int f = tid + it * 256;
        int row = f >> 3, colv = f & 7;
        *(float4*)(s + row * GP + colv * 4) = r[it];
    }
}

template <int EPI>
__global__ __launch_bounds__(256, 2) void tc_gemm(const float* __restrict__ Ain,
                                                  const float* __restrict__ bias,
                                                  float* __restrict__ Cout) {
    extern __shared__ float sm[];
    const float* A  = (EPI == 1) ? (const float*)g_y : Ain;
    const float* Bt = (EPI == 1) ? (const float*)g_wt_proj : (const float*)g_wt_qkv;

    const int tid = threadIdx.x;
    const int wid = tid >> 5, lid = tid & 31;
    const int wm = wid >> 2, wn = wid & 3;
    const int g = lid >> 2, q = lid & 3;
    const int cRow = blockIdx.y, cCol = blockIdx.x;

    const float* Abase = A  + (size_t)cRow * 128 * CDIM;
    const float* Bbase = Bt + (size_t)cCol * 128 * CDIM;

    float4 ra[4], rb[4];
    if (EPI == 0) gloadA_perm(Abase, 0, tid, ra); else gload(Abase, 0, tid, ra);
    gload(Bbase, 0, tid, rb);
    sstore(sm + SA0F, tid, ra);
    sstore(sm + SB0F, tid, rb);
    __syncthreads();

    float acc[4][4][4];
    #pragma unroll
    for (int i = 0; i < 4; i++)
        #pragma unroll
        for (int j = 0; j < 4; j++)
            #pragma unroll
            for (int r = 0; r < 4; r++) acc[i][j][r] = 0.0f;

    #pragma unroll 1
    for (int c = 0; c < 8; c++) {
        if (c < 7) {
            if (EPI == 0) gloadA_perm(Abase, (c + 1) * 32, tid, ra);
            else          gload(Abase, (c + 1) * 32, tid, ra);
            gload(Bbase, (c + 1) * 32, tid, rb);
        }
        const float* as = sm + ((c & 1) ? SA1F : SA0F);
        const float* bs = sm + ((c & 1) ? SB1F : SB0F);

        #pragma unroll
        for (int ks = 0; ks < 4; ks++) {
            const int kc = ks * 8 + 2 * q;
            float2 bb[4];
            #pragma unroll
            for (int j = 0; j < 4; j++)
                bb[j] = *(const float2*)(bs + (wn * 32 + j * 8 + g) * GP + kc);
            #pragma unroll
            for (int i = 0; i < 4; i++) {
                const float* ap = as + (wm * 64 + i * 16 + g) * GP + kc;
                float2 aA = *(const float2*)ap;             // a0, a2
                float2 aB = *(const float2*)(ap + 8 * GP);  // a1, a3
                uint32_t a0 = __float_as_uint(aA.x), a2 = __float_as_uint(aA.y);
                uint32_t a1 = __float_as_uint(aB.x), a3 = __float_as_uint(aB.y);
                #pragma unroll
                for (int j = 0; j < 4; j++)
                    MMA_TF32(acc[i][j], a0, a1, a2, a3,
                             __float_as_uint(bb[j].x), __float_as_uint(bb[j].y));
            }
        }

        if (c < 7) {
            sstore(sm + ((c & 1) ? SA0F : SA1F), tid, ra);
            sstore(sm + ((c & 1) ? SB0F : SB1F), tid, rb);
        }
        __syncthreads();
    }

    const int nbase = cCol * 128 + wn * 32;
    float bv[4][2];
    #pragma unroll
    for (int j = 0; j < 4; j++) {
        int n = nbase + j * 8 + 2 * q;
        bv[j][0] = __ldg(bias + n);
        bv[j][1] = __ldg(bias + n + 1);
    }

    if (EPI == 0) {
        const int t = nbase >> 8;
        const int h = (nbase >> 5) & 7;
        const float sc = (t == 0) ? 0.17677669529663687f : 1.0f;
        float* gdst = (t == 0) ? g_q : (t == 1) ? g_k : g_v;
        #pragma unroll
        for (int i = 0; i < 4; i++) {
            #pragma unroll
            for (int rr = 0; rr < 2; rr++) {
                int m = cRow * 128 + wm * 64 + i * 16 + g + rr * 8;
                int bwin = m / NTOK;
                int nn = m - bwin * NTOK;
                float* dst = gdst + (((size_t)(bwin * HEADS + h) * NTOK + nn) * HD);
                #pragma unroll
                for (int j = 0; j < 4; j++) {
                    float2 o;
                    o.x = (acc[i][j][rr * 2 + 0] + bv[j][0]) * sc;
                    o.y = (acc[i][j][rr * 2 + 1] + bv[j][1]) * sc;
                    *(float2*)(dst + j * 8 + 2 * q) = o;
                }
            }
        }
    } else {
        #pragma unroll
        for (int i = 0; i < 4; i++) {
            #pragma unroll
            for (int rr = 0; rr < 2; rr++) {
                int m = cRow * 128 + wm * 64 + i * 16 + g + rr * 8;
                float* dst = Cout + (size_t)m * CDIM + nbase;
                #pragma unroll
                for (int j = 0; j < 4; j++) {
                    float2 o;
                    o.x = acc[i][j][rr * 2 + 0] + bv[j][0];
                    o.y = acc[i][j][rr * 2 + 1] + bv[j][1];
                    *(float2*)(dst + j * 8 + 2 * q) = o;
                }
            }
        }
    }
}

// ---------------------------------------------------------------------------
// MMA flash attention: 64 threads per (window, head). Queries padded 49->64,
// keys 49->56. BM read direct from L2 as bf16x2 (prefetched before QK mma).
// Output written to g_y tf32-rounded AND k-permuted (proj consumes directly).
// smem: Q[64][36] | K[56][36] | Vt[32][60]; P[64][60] aliases Q+K region.
// ---------------------------------------------------------------------------
#define PITCH 36
#define QS_OFF  0
#define KS_OFF  2304
#define VTS_OFF 4320
#define SM_FLOATS 6240

__global__ __launch_bounds__(64) void attn_mma_kernel() {
    __shared__ float sm[SM_FLOATS];
    float* Qs  = sm + QS_OFF;    // [64][36]
    float* Ks  = sm + KS_OFF;    // [56][36]
    float* Vts = sm + VTS_OFF;   // [32][60]
    float* Ps  = sm;             // [64][60] aliases Q+K after sync (3840 <= 4320)

    const int blk = blockIdx.x;          // b*8 + h
    const int b = blk >> 3, h = blk & 7;
    const int tid = threadIdx.x, wid = tid >> 5, lid = tid & 31;
    const int g = lid >> 2, q = lid & 3;
    const int rbase = wid * 32;

    const size_t base4 = (size_t)blk * (NTOK * HD / 4);
    const float4* qg4 = ((const float4*)g_q) + base4;
    const float4* kg4 = ((const float4*)g_k) + base4;
    const float4* vg4 = ((const float4*)g_v) + base4;
    const float4 z4 = make_float4(0.f, 0.f, 0.f, 0.f);

    for (int t = tid; t < 512; t += 64) {
        int row = t >> 3, c = t & 7;
        *(float4*)(Qs + row * PITCH + c * 4) = (row < NTOK) ? qg4[t] : z4;
    }
    for (int t = tid; t < 448; t += 64) {
        int row = t >> 3, c = t & 7;
        float4 kv = (row < NTOK) ? kg4[t] : z4;
        *(float4*)(Ks + row * PITCH + c * 4) = kv;
        float4 vv = (row < NTOK) ? vg4[t] : z4;
        Vts[(c * 4 + 0) * 60 + row] = vv.x;
        Vts[(c * 4 + 1) * 60 + row] = vv.y;
        Vts[(c * 4 + 2) * 60 + row] = vv.z;
        Vts[(c * 4 + 3) * 60 + row] = vv.w;
    }
    __syncthreads();

    // ---- prefetch bias+mask (bf16x2) while QK mma runs ----
    const __nv_bfloat16* bmg = g_bm + ((size_t)((b & (NWIN - 1)) * HEADS + h)) * (64 * 56);
    uint32_t bmr[2][2][7];
    #pragma unroll
    for (int mi = 0; mi < 2; mi++) {
        const int r0 = rbase + mi * 16 + g;
        #pragma unroll
        for (int nj = 0; nj < 7; nj++) {
            const int cc = nj * 8 + 2 * q;
            bmr[mi][0][nj] = *(const uint32_t*)(bmg + r0 * 56 + cc);
            bmr[mi][1][nj] = *(const uint32_t*)(bmg + (r0 + 8) * 56 + cc);
        }
    }

    // ---- QK^T ----
    float s[2][7][4];
    #pragma unroll
    for (int mi = 0; mi < 2; mi++)
        #pragma unroll
        for (int nj = 0; nj < 7; nj++)
            #pragma unroll
            for (int r = 0; r < 4; r++) s[mi][nj][r] = 0.0f;

    #pragma unroll
    for (int ks = 0; ks < 4; ks++) {
        const int kc = ks * 8 + q;
        uint32_t b0[7], b1[7];
        #pragma unroll
        for (int nj = 0; nj < 7; nj++) {
            const float* bp = Ks + (nj * 8 + g) * PITCH + kc;
            b0[nj] = __float_as_uint(bp[0]);
            b1[nj] = __float_as_uint(bp[4]);
        }
        #pragma unroll
        for (int mi = 0; mi < 2; mi++) {
            const float* ap = Qs + (rbase + mi * 16 + g) * PITCH + kc;
            uint32_t a0 = __float_as_uint(ap[0]);
            uint32_t a2 = __float_as_uint(ap[4]);
            uint32_t a1 = __float_as_uint(ap[8 * PITCH]);
            uint32_t a3 = __float_as_uint(ap[8 * PITCH + 4]);
            #pragma unroll
            for (int nj = 0; nj < 7; nj++)
                MMA_TF32(s[mi][nj], a0, a1, a2, a3, b0[nj], b1[nj]);
        }
    }

    // ---- softmax (bias+mask add, exp, row sums) ----
    float inv[2][2];
    #pragma unroll
    for (int mi = 0; mi < 2; mi++) {
        float l0 = 0.0f, l1 = 0.0f;
        #pragma unroll
        for (int nj = 0; nj < 7; nj++) {
            float2 bmA = __bfloat1622float2(*(__nv_bfloat162*)&bmr[mi][0][nj]);
            float2 bmB = __bfloat1622float2(*(__nv_bfloat162*)&bmr[mi][1][nj]);
            float e0 = __expf(s[mi][nj][0] + bmA.x);
            float e1 = __expf(s[mi][nj][1] + bmA.y);
            float e2 = __expf(s[mi][nj][2] + bmB.x);
            float e3 = __expf(s[mi][nj][3] + bmB.y);
            s[mi][nj][0] = e0; s[mi][nj][1] = e1;
            s[mi][nj][2] = e2; s[mi][nj][3] = e3;
            l0 += e0 + e1;
            l1 += e2 + e3;
        }
        l0 += __shfl_xor_sync(0xffffffffu, l0, 1);
        l0 += __shfl_xor_sync(0xffffffffu, l0, 2);
        l1 += __shfl_xor_sync(0xffffffffu, l1, 1);
        l1 += __shfl_xor_sync(0xffffffffu, l1, 2);
        inv[mi][0] = 1.0f / l0;
        inv[mi][1] = 1.0f / l1;
    }

    __syncthreads();   // both warps done reading Qs/Ks before P overwrites

    // ---- stage P ----
    #pragma unroll
    for (int mi = 0; mi < 2; mi++) {
        const int r0 = rbase + mi * 16 + g;
        #pragma unroll
        for (int nj = 0; nj < 7; nj++) {
            const int cc = nj * 8 + 2 * q;
            *(float2*)(Ps + r0 * 60 + cc)       = make_float2(s[mi][nj][0], s[mi][nj][1]);
            *(float2*)(Ps + (r0 + 8) * 60 + cc) = make_float2(s[mi][nj][2], s[mi][nj][3]);
        }
    }
    __syncwarp();

    // ---- P x V ----
    float o[2][4][4];
    #pragma unroll
    for (int mi = 0; mi < 2; mi++)
        #pragma unroll
        for (int nj = 0; nj < 4; nj++)
            #pragma unroll
            for (int r = 0; r < 4; r++) o[mi][nj][r] = 0.0f;

    #pragma unroll
    for (int ks = 0; ks < 7; ks++) {
        const int kc = ks * 8 + q;
        uint32_t b0[4], b1[4];
        #pragma unroll
        for (int nj = 0; nj < 4; nj++) {
            const float* bp = Vts + (nj * 8 + g) * 60 + kc;
            b0[nj] = __float_as_uint(bp[0]);
            b1[nj] = __float_as_uint(bp[4]);
        }
        #pragma unroll
        for (int mi = 0; mi < 2; mi++) {
            const float* ap = Ps + (rbase + mi * 16 + g) * 60 + kc;
            uint32_t a0 = __float_as_uint(ap[0]);
            uint32_t a2 = __float_as_uint(ap[4]);
            uint32_t a1 = __float_as_uint(ap[8 * 60]);
            uint32_t a3 = __float_as_uint(ap[8 * 60 + 4]);
            #pragma unroll
            for (int nj = 0; nj < 4; nj++)
                MMA_TF32(o[mi][nj], a0, a1, a2, a3, b0[nj], b1[nj]);
        }
    }

    // ---- normalize + store to g_y (tf32-rounded, k-permuted) ----
    const int p0 = ((q & 1) << 2) | (q >> 1);   // phys col of logical 2q; +2 for 2q+1
    #pragma unroll
    for (int mi = 0; mi < 2; mi++) {
        #pragma unroll
        for (int rr = 0; rr < 2; rr++) {
            const int row = rbase + mi * 16 + g + rr * 8;
            if (row < NTOK) {
                const float iv = inv[mi][rr];
                float* dst = g_y + ((size_t)b * NTOK + row) * CDIM + h * HD;
                #pragma unroll
                for (int nj = 0; nj < 4; nj++) {
                    dst[nj * 8 + p0]     = to_tf32(o[mi][nj][rr * 2 + 0] * iv);
                    dst[nj * 8 + p0 + 2] = to_tf32(o[mi][nj][rr * 2 + 1] * iv);
                }
            }
        }
    }
}

// ---------------------------------------------------------------------------
// Launch
// ---------------------------------------------------------------------------
extern "C" void kernel_launch(void* const* d_in, const int* in_sizes, int n_in,
                              void* d_out, int out_size)
{
    const float* x          = (const float*)d_in[0];
    const float* mask       = (const float*)d_in[1];
    const float* qkv_w      = (const float*)d_in[2];
    const float* qkv_b      = (const float*)d_in[3];
    const float* bias_table = (const float*)d_in[4];
    const float* proj_w     = (const float*)d_in[5];
    const float* proj_b     = (const float*)d_in[6];
    const int*   rel_idx    = (const int*)d_in[7];
    float* out = (float*)d_out;

    cudaFuncSetAttribute(tc_gemm<0>, cudaFuncAttributeMaxDynamicSharedMemorySize, SMTOT_BYTES);
    cudaFuncSetAttribute(tc_gemm<1>, cudaFuncAttributeMaxDynamicSharedMemorySize, SMTOT_BYTES);

    // 0) weight transposes (tf32, k-permuted) + bf16 bias+mask table
    transpose_kernel<<<dim3(QKV_N / 32, CDIM / 32), dim3(32, 8)>>>(qkv_w, CDIM, QKV_N, 0);
    transpose_kernel<<<dim3(CDIM / 32, CDIM / 32), dim3(32, 8)>>>(proj_w, CDIM, CDIM, 1);
    bm_kernel<<<NWIN * HEADS, 256>>>(bias_table, mask, rel_idx);

    // 1) QKV: [200704 x 256] x [256 x 768] -> g_q/g_k/g_v
    tc_gemm<0><<<dim3(QKV_N / 128, M_TOTAL / 128), 256, SMTOT_BYTES>>>(x, qkv_b, nullptr);

    // 2) attention -> g_y (permuted+rounded)
    attn_mma_kernel<<<BATCH * HEADS, 64>>>();

    // 3) proj: g_y x [256 x 256] -> out
    tc_gemm<1><<<dim3(CDIM / 128, M_TOTAL / 128), 256, SMTOT_BYTES>>>(nullptr, proj_b, out);
}

// round 10
// speedup vs baseline: 3.4647x; 1.0416x over previous
#include <cuda_runtime.h>
#include <cuda_bf16.h>
#include <cstdint>

// Problem constants
#define HEADS   8
#define NTOK    49
#define CDIM    256
#define HD      32
#define BATCH   4096
#define NWIN    64
#define M_TOTAL (BATCH * NTOK)      // 200704
#define QKV_N   768

// ---------------------------------------------------------------------------
// Scratch (__device__ globals; allocation-free rule)
// ---------------------------------------------------------------------------
__device__ float g_xr[(size_t)M_TOTAL * CDIM];              // x, tf32-rounded
__device__ float g_q[(size_t)BATCH * HEADS * NTOK * HD];
__device__ float g_k[(size_t)BATCH * HEADS * NTOK * HD];
__device__ float g_v[(size_t)BATCH * HEADS * NTOK * HD];
__device__ float g_y[(size_t)M_TOTAL * CDIM];               // attn out, tf32-rounded
__device__ float g_wt_qkv[(size_t)QKV_N * CDIM];            // W^T, tf32
__device__ float g_wt_proj[(size_t)CDIM * CDIM];            // W^T, tf32
__device__ __nv_bfloat16 g_bm[(size_t)NWIN * HEADS * 64 * 56]; // bias+mask bf16

__device__ __forceinline__ float to_tf32(float x) {
    float r;
    asm("cvt.rna.tf32.f32 %0, %1;" : "=f"(r) : "f"(x));
    return r;
}
__device__ __forceinline__ uint32_t smem_u32(const void* p) {
    uint32_t a;
    asm("{ .reg .u64 t; cvta.to.shared.u64 t, %1; cvt.u32.u64 %0, t; }" : "=r"(a) : "l"(p));
    return a;
}
__device__ __forceinline__ void cp_async16(uint32_t saddr, const void* gaddr) {
    asm volatile("cp.async.cg.shared.global [%0], [%1], 16;" :: "r"(saddr), "l"(gaddr));
}
#define CP_COMMIT() asm volatile("cp.async.commit_group;" ::: "memory")
#define CP_WAIT1()  asm volatile("cp.async.wait_group 1;" ::: "memory")
#define CP_WAIT0()  asm volatile("cp.async.wait_group 0;" ::: "memory")

#define MMA_TF32(acc, a0, a1, a2, a3, b0, b1) \
    asm volatile("mma.sync.aligned.m16n8k8.row.col.f32.tf32.tf32.f32 " \
        "{%0,%1,%2,%3}, {%4,%5,%6,%7}, {%8,%9}, {%0,%1,%2,%3};" \
        : "+f"((acc)[0]), "+f"((acc)[1]), "+f"((acc)[2]), "+f"((acc)[3]) \
        : "r"(a0), "r"(a1), "r"(a2), "r"(a3), "r"(b0), "r"(b1))

// ---------------------------------------------------------------------------
// Prepass: round x -> g_xr (tf32 rna), pure streaming
// ---------------------------------------------------------------------------
__global__ __launch_bounds__(256) void round_x_kernel(const float4* __restrict__ x) {
    size_t i = (size_t)blockIdx.x * 1024 + threadIdx.x;
    float4* dst = (float4*)g_xr;
    #pragma unroll
    for (int it = 0; it < 4; it++, i += 256) {
        float4 v = x[i];
        dst[i] = make_float4(to_tf32(v.x), to_tf32(v.y), to_tf32(v.z), to_tf32(v.w));
    }
}

// ---------------------------------------------------------------------------
// Weight transpose: W[K][N] -> Wt[N][K], tf32-rounded
// ---------------------------------------------------------------------------
__global__ void transpose_kernel(const float* __restrict__ W, int K, int N, int sel) {
    float* Wt = sel ? g_wt_proj : g_wt_qkv;
    __shared__ float t[32][33];
    int bn = blockIdx.x * 32, bk = blockIdx.y * 32;
    int x = threadIdx.x, y = threadIdx.y;
    #pragma unroll
    for (int i = 0; i < 32; i += 8)
        t[y + i][x] = W[(size_t)(bk + y + i) * N + bn + x];
    __syncthreads();
    #pragma unroll
    for (int i = 0; i < 32; i += 8)
        Wt[(size_t)(bn + y + i) * K + bk + x] = to_tf32(t[x][y + i]);
}

// ---------------------------------------------------------------------------
// bias+mask precompute -> bf16, rows padded to 64, cols to 56 (-30 pad)
// ---------------------------------------------------------------------------
__global__ void bm_kernel(const float* __restrict__ bias_table,
                          const float* __restrict__ mask,
                          const int*   __restrict__ rel_idx) {
    const int w = blockIdx.x >> 3, h = blockIdx.x & 7;
    __nv_bfloat16* dst = g_bm + (size_t)blockIdx.x * (64 * 56);
    for (int t = threadIdx.x; t < 64 * 56; t += 256) {
        int i = t / 56, j = t - i * 56;
        float v = -30.0f;
        if (i < NTOK && j < NTOK)
            v = bias_table[rel_idx[i * NTOK + j] * HEADS + h]
              + mask[((size_t)w * NTOK + i) * NTOK + j];
        dst[t] = __float2bfloat16(v);
    }
}

// ---------------------------------------------------------------------------
// tf32 mma.sync GEMM, BM=128,BN=128,BK=32, 8 warps, cp.async 3-stage pipeline.
// A and B both pre-rounded to tf32 in global -> pure LDGSTS staging, no cvt.
// smem: 3 stages x (A[128][36] + B[128][36]) = 108 KB.
// ---------------------------------------------------------------------------
#define PITCH 36
#define STAGE_F 4608                 // floats per tile (128*36)
#define STAGE_B 18432                // bytes per tile
#define SMTOT_BYTES (3 * 2 * STAGE_B) // 110592

template <int EPI>
__global__ __launch_bounds__(256, 2) void tc_gemm(const float* __restrict__ bias,
                                                  float* __restrict__ Cout) {
    extern __shared__ float sm[];
    const uint32_t sbase = smem_u32(sm);
    const float* A  = (EPI == 1) ? (const float*)g_y : (const float*)g_xr;
    const float* Bt = (EPI == 1) ? (const float*)g_wt_proj : (const float*)g_wt_qkv;

    const int tid = threadIdx.x;
    const int wid = tid >> 5, lid = tid & 31;
    const int wm = wid >> 2, wn = wid & 3;
    const int g = lid >> 2, q = lid & 3;
    const int cRow = blockIdx.y, cCol = blockIdx.x;

    // per-thread staging coordinates: 4 x 16B per tile per stage
    const int f0row = tid >> 3;            // 0..31 (+ it*32)
    const int f0col = (tid & 7) * 4;       // 0,4,..,28
    const float* Ap = A  + (size_t)(cRow * 128 + f0row) * CDIM + f0col;
    const float* Bp = Bt + (size_t)(cCol * 128 + f0row) * CDIM + f0col;
    const uint32_t soff = (uint32_t)(f0row * PITCH + f0col) * 4;

    #define ISSUE_STAGE(c, s) do { \
        uint32_t _sa = sbase + (uint32_t)(s) * (2 * STAGE_B) + soff; \
        uint32_t _sb = _sa + STAGE_B; \
        const float* _ap = Ap + (c) * 32; \
        const float* _bp = Bp + (c) * 32; \
        _Pragma("unroll") \
        for (int _it = 0; _it < 4; _it++) { \
            cp_async16(_sa + _it * (32 * PITCH * 4), _ap + (size_t)_it * 32 * CDIM); \
            cp_async16(_sb + _it * (32 * PITCH * 4), _bp + (size_t)_it * 32 * CDIM); \
        } \
        CP_COMMIT(); \
    } while (0)

    ISSUE_STAGE(0, 0);
    ISSUE_STAGE(1, 1);

    float acc[4][4][4];
    #pragma unroll
    for (int i = 0; i < 4; i++)
        #pragma unroll
        for (int j = 0; j < 4; j++)
            #pragma unroll
            for (int r = 0; r < 4; r++) acc[i][j][r] = 0.0f;

    int stage = 0;
    #pragma unroll 1
    for (int c = 0; c < 8; c++) {
        if (c >= 7) { CP_WAIT0(); } else { CP_WAIT1(); }
        __syncthreads();
        if (c < 6) {
            int ns = stage + 2;
            if (ns >= 3) ns -= 3;
            ISSUE_STAGE(c + 2, ns);
        }

        const float* as = sm + stage * (2 * STAGE_F);
        const float* bs = as + STAGE_F;

        #pragma unroll
        for (int ks = 0; ks < 4; ks++) {
            const int kc = ks * 8 + q;
            uint32_t b0[4], b1[4];
            #pragma unroll
            for (int j = 0; j < 4; j++) {
                const float* bp = bs + (wn * 32 + j * 8 + g) * PITCH + kc;
                b0[j] = __float_as_uint(bp[0]);
                b1[j] = __float_as_uint(bp[4]);
            }
            #pragma unroll
            for (int i = 0; i < 4; i++) {
                const float* ap = as + (wm * 64 + i * 16 + g) * PITCH + kc;
                uint32_t a0 = __float_as_uint(ap[0]);
                uint32_t a2 = __float_as_uint(ap[4]);
                uint32_t a1 = __float_as_uint(ap[8 * PITCH]);
                uint32_t a3 = __float_as_uint(ap[8 * PITCH + 4]);
                #pragma unroll
                for (int j = 0; j < 4; j++)
                    MMA_TF32(acc[i][j], a0, a1, a2, a3, b0[j], b1[j]);
            }
        }
        __syncthreads();
        if (++stage >= 3) stage = 0;
    }

    // ------------------- epilogue -------------------
    const int nbase = cCol * 128 + wn * 32;
    float bv[4][2];
    #pragma unroll
    for (int j = 0; j < 4; j++) {
        int n = nbase + j * 8 + 2 * q;
        bv[j][0] = __ldg(bias + n);
        bv[j][1] = __ldg(bias + n + 1);
    }

    if (EPI == 0) {
        const int t = nbase >> 8;
        const int h = (nbase >> 5) & 7;
        const float sc = (t == 0) ? 0.17677669529663687f : 1.0f;
        float* gdst = (t == 0) ? g_q : (t == 1) ? g_k : g_v;
        #pragma unroll
        for (int i = 0; i < 4; i++) {
            #pragma unroll
            for (int rr = 0; rr < 2; rr++) {
                int m = cRow * 128 + wm * 64 + i * 16 + g + rr * 8;
                int bwin = m / NTOK;
                int nn = m - bwin * NTOK;
                float* dst = gdst + (((size_t)(bwin * HEADS + h) * NTOK + nn) * HD);
                #pragma unroll
                for (int j = 0; j < 4; j++) {
                    float2 o;
                    o.x = (acc[i][j][rr * 2 + 0] + bv[j][0]) * sc;
                    o.y = (acc[i][j][rr * 2 + 1] + bv[j][1]) * sc;
                    *(float2*)(dst + j * 8 + 2 * q) = o;
                }
            }
        }
    } else {
        #pragma unroll
        for (int i = 0; i < 4; i++) {
            #pragma unroll
            for (int rr = 0; rr < 2; rr++) {
                int m = cRow * 128 + wm * 64 + i * 16 + g + rr * 8;
                float* dst = Cout + (size_t)m * CDIM + nbase;
                #pragma unroll
                for (int j = 0; j < 4; j++) {
                    float2 o;
                    o.x = acc[i][j][rr * 2 + 0] + bv[j][0];
                    o.y = acc[i][j][rr * 2 + 1] + bv[j][1];
                    *(float2*)(dst + j * 8 + 2 * q) = o;
                }
            }
        }
    }
}

// ---------------------------------------------------------------------------
// MMA flash attention: 64 threads per (window, head). Queries padded 49->64,
// keys 49->56. BM read direct from L2 as bf16x2 (prefetched before QK mma).
// Output written to g_y tf32-rounded (proj's cp.async consumes it directly).
// smem: Q[64][36] | K[56][36] | Vt[32][60]; P[64][60] aliases Q+K region.
// ---------------------------------------------------------------------------
#define QS_OFF  0
#define KS_OFF  2304
#define VTS_OFF 4320
#define SM_FLOATS 6240

__global__ __launch_bounds__(64) void attn_mma_kernel() {
    __shared__ float sm[SM_FLOATS];
    float* Qs  = sm + QS_OFF;    // [64][36]
    float* Ks  = sm + KS_OFF;    // [56][36]
    float* Vts = sm + VTS_OFF;   // [32][60]
    float* Ps  = sm;             // [64][60] aliases Q+K after sync

    const int blk = blockIdx.x;          // b*8 + h
    const int b = blk >> 3, h = blk & 7;
    const int tid = threadIdx.x, wid = tid >> 5, lid = tid & 31;
    const int g = lid >> 2, q = lid & 3;
    const int rbase = wid * 32;

    const size_t base4 = (size_t)blk * (NTOK * HD / 4);
    const float4* qg4 = ((const float4*)g_q) + base4;
    const float4* kg4 = ((const float4*)g_k) + base4;
    const float4* vg4 = ((const float4*)g_v) + base4;
    const float4 z4 = make_float4(0.f, 0.f, 0.f, 0.f);

    for (int t = tid; t < 512; t += 64) {
        int row = t >> 3, c = t & 7;
        *(float4*)(Qs + row * PITCH + c * 4) = (row < NTOK) ? qg4[t] : z4;
    }
    for (int t = tid; t < 448; t += 64) {
        int row = t >> 3, c = t & 7;
        float4 kv = (row < NTOK) ? kg4[t] : z4;
        *(float4*)(Ks + row * PITCH + c * 4) = kv;
        float4 vv = (row < NTOK) ? vg4[t] : z4;
        Vts[(c * 4 + 0) * 60 + row] = vv.x;
        Vts[(c * 4 + 1) * 60 + row] = vv.y;
        Vts[(c * 4 + 2) * 60 + row] = vv.z;
        Vts[(c * 4 + 3) * 60 + row] = vv.w;
    }
    __syncthreads();

    // ---- prefetch bias+mask (bf16x2) while QK mma runs ----
    const __nv_bfloat16* bmg = g_bm + ((size_t)((b & (NWIN - 1)) * HEADS + h)) * (64 * 56);
    uint32_t bmr[2][2][7];
    #pragma unroll
    for (int mi = 0; mi < 2; mi++) {
        const int r0 = rbase + mi * 16 + g;
        #pragma unroll
        for (int nj = 0; nj < 7; nj++) {
            const int cc = nj * 8 + 2 * q;
            bmr[mi][0][nj] = *(const uint32_t*)(bmg + r0 * 56 + cc);
            bmr[mi][1][nj] = *(const uint32_t*)(bmg + (r0 + 8) * 56 + cc);
        }
    }

    // ---- QK^T ----
    float s[2][7][4];
    #pragma unroll
    for (int mi = 0; mi < 2; mi++)
        #pragma unroll
        for (int nj = 0; nj < 7; nj++)
            #pragma unroll
            for (int r = 0; r < 4; r++) s[mi][nj][r] = 0.0f;

    #pragma unroll
    for (int ks = 0; ks < 4; ks++) {
        const int kc = ks * 8 + q;
        uint32_t b0[7], b1[7];
        #pragma unroll
        for (int nj = 0; nj < 7; nj++) {
            const float* bp = Ks + (nj * 8 + g) * PITCH + kc;
            b0[nj] = __float_as_uint(bp[0]);
            b1[nj] = __float_as_uint(bp[4]);
        }
        #pragma unroll
        for (int mi = 0; mi < 2; mi++) {
            const float* ap = Qs + (rbase + mi * 16 + g) * PITCH + kc;
            uint32_t a0 = __float_as_uint(ap[0]);
            uint32_t a2 = __float_as_uint(ap[4]);
            uint32_t a1 = __float_as_uint(ap[8 * PITCH]);
            uint32_t a3 = __float_as_uint(ap[8 * PITCH + 4]);
            #pragma unroll
            for (int nj = 0; nj < 7; nj++)
                MMA_TF32(s[mi][nj], a0, a1, a2, a3, b0[nj], b1[nj]);
        }
    }

    // ---- softmax ----
    float inv[2][2];
    #pragma unroll
    for (int mi = 0; mi < 2; mi++) {
        float l0 = 0.0f, l1 = 0.0f;
        #pragma unroll
        for (int nj = 0; nj < 7; nj++) {
            float2 bmA = __bfloat1622float2(*(__nv_bfloat162*)&bmr[mi][0][nj]);
            float2 bmB = __bfloat1622float2(*(__nv_bfloat162*)&bmr[mi][1][nj]);
            float e0 = __expf(s[mi][nj][0] + bmA.x);
            float e1 = __expf(s[mi][nj][1] + bmA.y);
            float e2 = __expf(s[mi][nj][2] + bmB.x);
            float e3 = __expf(s[mi][nj][3] + bmB.y);
            s[mi][nj][0] = e0; s[mi][nj][1] = e1;
            s[mi][nj][2] = e2; s[mi][nj][3] = e3;
            l0 += e0 + e1;
            l1 += e2 + e3;
        }
        l0 += __shfl_xor_sync(0xffffffffu, l0, 1);
        l0 += __shfl_xor_sync(0xffffffffu, l0, 2);
        l1 += __shfl_xor_sync(0xffffffffu, l1, 1);
        l1 += __shfl_xor_sync(0xffffffffu, l1, 2);
        inv[mi][0] = 1.0f / l0;
        inv[mi][1] = 1.0f / l1;
    }

    __syncthreads();   // both warps done reading Qs/Ks before P overwrites

    // ---- stage P ----
    #pragma unroll
    for (int mi = 0; mi < 2; mi++) {
        const int r0 = rbase + mi * 16 + g;
        #pragma unroll
        for (int nj = 0; nj < 7; nj++) {
            const int cc = nj * 8 + 2 * q;
            *(float2*)(Ps + r0 * 60 + cc)       = make_float2(s[mi][nj][0], s[mi][nj][1]);
            *(float2*)(Ps + (r0 + 8) * 60 + cc) = make_float2(s[mi][nj][2], s[mi][nj][3]);
        }
    }
    __syncwarp();

    // ---- P x V ----
    float o[2][4][4];
    #pragma unroll
    for (int mi = 0; mi < 2; mi++)
        #pragma unroll
        for (int nj = 0; nj < 4; nj++)
            #pragma unroll
            for (int r = 0; r < 4; r++) o[mi][nj][r] = 0.0f;

    #pragma unroll
    for (int ks = 0; ks < 7; ks++) {
        const int kc = ks * 8 + q;
        uint32_t b0[4], b1[4];
        #pragma unroll
        for (int nj = 0; nj < 4; nj++) {
            const float* bp = Vts + (nj * 8 + g) * 60 + kc;
            b0[nj] = __float_as_uint(bp[0]);
            b1[nj] = __float_as_uint(bp[4]);
        }
        #pragma unroll
        for (int mi = 0; mi < 2; mi++) {
            const float* ap = Ps + (rbase + mi * 16 + g) * 60 + kc;
            uint32_t a0 = __float_as_uint(ap[0]);
            uint32_t a2 = __float_as_uint(ap[4]);
            uint32_t a1 = __float_as_uint(ap[8 * 60]);
            uint32_t a3 = __float_as_uint(ap[8 * 60 + 4]);
            #pragma unroll
            for (int nj = 0; nj < 4; nj++)
                MMA_TF32(o[mi][nj], a0, a1, a2, a3, b0[nj], b1[nj]);
        }
    }

    // ---- normalize + store to g_y (tf32-rounded, plain layout) ----
    #pragma unroll
    for (int mi = 0; mi < 2; mi++) {
        #pragma unroll
        for (int rr = 0; rr < 2; rr++) {
            const int row = rbase + mi * 16 + g + rr * 8;
            if (row < NTOK) {
                const float iv = inv[mi][rr];
                float* dst = g_y + ((size_t)b * NTOK + row) * CDIM + h * HD;
                #pragma unroll
                for (int nj = 0; nj < 4; nj++) {
                    float2 ov;
                    ov.x = to_tf32(o[mi][nj][rr * 2 + 0] * iv);
                    ov.y = to_tf32(o[mi][nj][rr * 2 + 1] * iv);
                    *(float2*)(dst + nj * 8 + 2 * q) = ov;
                }
            }
        }
    }
}

// ---------------------------------------------------------------------------
// Launch
// ---------------------------------------------------------------------------
extern "C" void kernel_launch(void* const* d_in, const int* in_sizes, int n_in,
                              void* d_out, int out_size)
{
    const float* x          = (const float*)d_in[0];
    const float* mask       = (const float*)d_in[1];
    const float* qkv_w      = (const float*)d_in[2];
    const float* qkv_b      = (const float*)d_in[3];
    const float* bias_table = (const float*)d_in[4];
    const float* proj_w     = (const float*)d_in[5];
    const float* proj_b     = (const float*)d_in[6];
    const int*   rel_idx    = (const int*)d_in[7];
    float* out = (float*)d_out;

    cudaFuncSetAttribute(tc_gemm<0>, cudaFuncAttributeMaxDynamicSharedMemorySize, SMTOT_BYTES);
    cudaFuncSetAttribute(tc_gemm<1>, cudaFuncAttributeMaxDynamicSharedMemorySize, SMTOT_BYTES);

    // 0) prepass: round x; weight transposes; bf16 bias+mask table
    round_x_kernel<<<M_TOTAL * CDIM / 4096, 256>>>((const float4*)x);
    transpose_kernel<<<dim3(QKV_N / 32, CDIM / 32), dim3(32, 8)>>>(qkv_w, CDIM, QKV_N, 0);
    transpose_kernel<<<dim3(CDIM / 32, CDIM / 32), dim3(32, 8)>>>(proj_w, CDIM, CDIM, 1);
    bm_kernel<<<NWIN * HEADS, 256>>>(bias_table, mask, rel_idx);

    // 1) QKV: g_xr [200704 x 256] x [256 x 768] -> g_q/g_k/g_v
    tc_gemm<0><<<dim3(QKV_N / 128, M_TOTAL / 128), 256, SMTOT_BYTES>>>(qkv_b, nullptr);

    // 2) attention -> g_y (tf32-rounded)
    attn_mma_kernel<<<BATCH * HEADS, 64>>>();

    // 3) proj: g_y x [256 x 256] -> out
    tc_gemm<1><<<dim3(CDIM / 128, M_TOTAL / 128), 256, SMTOT_BYTES>>>(proj_b, out);
}

// round 12
// speedup vs baseline: 3.7301x; 1.0766x over previous
#include <cuda_runtime.h>
#include <cuda_bf16.h>
#include <cstdint>

// Problem constants
#define HEADS   8
#define NTOK    49
#define CDIM    256
#define HD      32
#define BATCH   4096
#define NWIN    64
#define M_TOTAL (BATCH * NTOK)      // 200704
#define QKV_N   768

// ---------------------------------------------------------------------------
// Scratch (__device__ globals; allocation-free rule)
// ---------------------------------------------------------------------------
__device__ float g_xr[(size_t)M_TOTAL * CDIM];              // x, tf32-rounded, k-permuted
__device__ float g_q[(size_t)BATCH * HEADS * NTOK * HD];
__device__ float g_k[(size_t)BATCH * HEADS * NTOK * HD];
__device__ float g_v[(size_t)BATCH * HEADS * NTOK * HD];
__device__ float g_y[(size_t)M_TOTAL * CDIM];               // attn out, tf32-rounded, k-permuted
__device__ float g_wt_qkv[(size_t)QKV_N * CDIM];            // W^T, tf32, k-permuted
__device__ float g_wt_proj[(size_t)CDIM * CDIM];            // W^T, tf32, k-permuted
__device__ __nv_bfloat16 g_bm[(size_t)NWIN * HEADS * 64 * 56]; // bias+mask bf16

__device__ __forceinline__ float to_tf32(float x) {
    float r;
    asm("cvt.rna.tf32.f32 %0, %1;" : "=f"(r) : "f"(x));
    return r;
}
__device__ __forceinline__ uint32_t smem_u32(const void* p) {
    uint32_t a;
    asm("{ .reg .u64 t; cvta.to.shared.u64 t, %1; cvt.u32.u64 %0, t; }" : "=r"(a) : "l"(p));
    return a;
}
__device__ __forceinline__ void cp_async16(uint32_t saddr, const void* gaddr) {
    asm volatile("cp.async.cg.shared.global [%0], [%1], 16;" :: "r"(saddr), "l"(gaddr));
}
#define CP_COMMIT() asm volatile("cp.async.commit_group;" ::: "memory")
#define CP_WAIT0()  asm volatile("cp.async.wait_group 0;" ::: "memory")

#define MMA_TF32(acc, a0, a1, a2, a3, b0, b1) \
    asm volatile("mma.sync.aligned.m16n8k8.row.col.f32.tf32.tf32.f32 " \
        "{%0,%1,%2,%3}, {%4,%5,%6,%7}, {%8,%9}, {%0,%1,%2,%3};" \
        : "+f"((acc)[0]), "+f"((acc)[1]), "+f"((acc)[2]), "+f"((acc)[3]) \
        : "r"(a0), "r"(a1), "r"(a2), "r"(a3), "r"(b0), "r"(b1))

// k-permutation within each 32-col chunk: logical k=8s+q+4h -> phys 8s+2q+h
__device__ __host__ __forceinline__ int kperm(int x) {
    return (x & 24) + ((x & 3) << 1) + ((x >> 2) & 1);
}

// ---------------------------------------------------------------------------
// Prepass: round x -> g_xr (tf32 rna), k-permuted layout
// ---------------------------------------------------------------------------
__global__ __launch_bounds__(256) void round_x_kernel(const float* __restrict__ x) {
    size_t i = (size_t)blockIdx.x * 1024 + threadIdx.x;   // float4 slot index
    float4* dst = (float4*)g_xr;
    #pragma unroll
    for (int it = 0; it < 4; it++, i += 256) {
        size_t row = i >> 6;            // 64 float4 per row
        int v = (int)(i & 63);          // float4 slot in row
        int chunk = v >> 3, w = v & 7;  // 32-col chunk, slot within chunk
        const float* p = x + row * CDIM + chunk * 32 + (w >> 1) * 8 + (w & 1) * 2;
        float2 lo = *(const float2*)p;         // logical k0, k0+1
        float2 hi = *(const float2*)(p + 4);   // logical k0+4, k0+5
        dst[i] = make_float4(to_tf32(lo.x), to_tf32(hi.x), to_tf32(lo.y), to_tf32(hi.y));
    }
}

// ---------------------------------------------------------------------------
// Weight transpose: W[K][N] -> Wt[N][kperm(K)], tf32-rounded
// ---------------------------------------------------------------------------
__global__ void transpose_kernel(const float* __restrict__ W, int K, int N, int sel) {
    float* Wt = sel ? g_wt_proj : g_wt_qkv;
    __shared__ float t[32][33];
    int bn = blockIdx.x * 32, bk = blockIdx.y * 32;
    int x = threadIdx.x, y = threadIdx.y;
    #pragma unroll
    for (int i = 0; i < 32; i += 8)
        t[y + i][x] = W[(size_t)(bk + y + i) * N + bn + x];
    __syncthreads();
    #pragma unroll
    for (int i = 0; i < 32; i += 8)
        Wt[(size_t)(bn + y + i) * K + bk + kperm(x)] = to_tf32(t[x][y + i]);
}

// ---------------------------------------------------------------------------
// bias+mask precompute -> bf16, rows padded to 64, cols to 56 (-30 pad)
// ---------------------------------------------------------------------------
__global__ void bm_kernel(const float* __restrict__ bias_table,
                          const float* __restrict__ mask,
                          const int*   __restrict__ rel_idx) {
    const int w = blockIdx.x >> 3, h = blockIdx.x & 7;
    __nv_bfloat16* dst = g_bm + (size_t)blockIdx.x * (64 * 56);
    for (int t = threadIdx.x; t < 64 * 56; t += 256) {
        int i = t / 56, j = t - i * 56;
        float v = -30.0f;
        if (i < NTOK && j < NTOK)
            v = bias_table[rel_idx[i * NTOK + j] * HEADS + h]
              + mask[((size_t)w * NTOK + i) * NTOK + j];
        dst[t] = __float2bfloat16(v);
    }
}

// ---------------------------------------------------------------------------
// tf32 mma.sync GEMM, BM=128,BN=128,BK=32, 8 warps.
// cp.async 2-stage pipeline, ONE __syncthreads per chunk.
// Global data k-permuted -> LDS.64 fragment gathers (pitch 40, conflict-free).
// smem: 2 stages x (A[128][40] + B[128][40]) = 80 KB.
// ---------------------------------------------------------------------------
#define GP 40
#define STAGE_F 5120                 // floats per tile (128*40)
#define STAGE_B 20480                // bytes per tile
#define SMTOT_BYTES (2 * 2 * STAGE_B) // 81920

template <int EPI>
__global__ __launch_bounds__(256, 2) void tc_gemm(const float* __restrict__ bias,
                                                  float* __restrict__ Cout) {
    extern __shared__ float sm[];
    const uint32_t sbase = smem_u32(sm);
    const float* A  = (EPI == 1) ? (const float*)g_y : (const float*)g_xr;
    const float* Bt = (EPI == 1) ? (const float*)g_wt_proj : (const float*)g_wt_qkv;

    const int tid = threadIdx.x;
    const int wid = tid >> 5, lid = tid & 31;
    const int wm = wid >> 2, wn = wid & 3;
    const int g = lid >> 2, q = lid & 3;
    const int cRow = blockIdx.y, cCol = blockIdx.x;

    // per-thread staging coordinates: 4 x 16B per tile per stage
    const int f0row = tid >> 3;            // 0..31 (+ it*32)
    const int f0col = (tid & 7) * 4;       // 0,4,..,28
    const float* Ap = A  + (size_t)(cRow * 128 + f0row) * CDIM + f0col;
    const float* Bp = Bt + (size_t)(cCol * 128 + f0row) * CDIM + f0col;
    const uint32_t soff = (uint32_t)(f0row * GP + f0col) * 4;

    #define ISSUE_STAGE(c, s) do { \
        uint32_t _sa = sbase + (uint32_t)(s) * (2 * STAGE_B) + soff; \
        uint32_t _sb = _sa + STAGE_B; \
        const float* _ap = Ap + (c) * 32; \
        const float* _bp = Bp + (c) * 32; \
        _Pragma("unroll") \
        for (int _it = 0; _it < 4; _it++) { \
            cp_async16(_sa + _it * (32 * GP * 4), _ap + (size_t)_it * 32 * CDIM); \
            cp_async16(_sb + _it * (32 * GP * 4), _bp + (size_t)_it * 32 * CDIM); \
        } \
        CP_COMMIT(); \
    } while (0)

    ISSUE_STAGE(0, 0);

    float acc[4][4][4];
    #pragma unroll
    for (int i = 0; i < 4; i++)
        #pragma unroll
        for (int j = 0; j < 4; j++)
            #pragma unroll
            for (int r = 0; r < 4; r++) acc[i][j][r] = 0.0f;

    #pragma unroll 1
    for (int c = 0; c < 8; c++) {
        CP_WAIT0();           // own chunk-c copies arrived
        __syncthreads();      // everyone's arrived; everyone done with chunk c-1
        if (c < 7) ISSUE_STAGE(c + 1, (c + 1) & 1);   // overlaps chunk-c mma

        const float* as = sm + (c & 1) * (2 * STAGE_F);
        const float* bs = as + STAGE_F;

        #pragma unroll
        for (int ks = 0; ks < 4; ks++) {
            const int kc = ks * 8 + 2 * q;
            float2 bb[4];
            #pragma unroll
            for (int j = 0; j < 4; j++)
                bb[j] = *(const float2*)(bs + (wn * 32 + j * 8 + g) * GP + kc);
            #pragma unroll
            for (int i = 0; i < 4; i++) {
                const float* ap = as + (wm * 64 + i * 16 + g) * GP + kc;
                float2 aA = *(const float2*)ap;             // a0, a2
                float2 aB = *(const float2*)(ap + 8 * GP);  // a1, a3
                uint32_t a0 = __float_as_uint(aA.x), a2 = __float_as_uint(aA.y);
                uint32_t a1 = __float_as_uint(aB.x), a3 = __float_as_uint(aB.y);
                #pragma unroll
                for (int j = 0; j < 4; j++)
                    MMA_TF32(acc[i][j], a0, a1, a2, a3,
                             __float_as_uint(bb[j].x), __float_as_uint(bb[j].y));
            }
        }
    }

    // ------------------- epilogue -------------------
    const int nbase = cCol * 128 + wn * 32;
    float bv[4][2];
    #pragma unroll
    for (int j = 0; j < 4; j++) {
        int n = nbase + j * 8 + 2 * q;
        bv[j][0] = __ldg(bias + n);
        bv[j][1] = __ldg(bias + n + 1);
    }

    if (EPI == 0) {
        const int t = nbase >> 8;
        const int h = (nbase >> 5) & 7;
        const float sc = (t == 0) ? 0.17677669529663687f : 1.0f;
        float* gdst = (t == 0) ? g_q : (t == 1) ? g_k : g_v;
        #pragma unroll
        for (int i = 0; i < 4; i++) {
            #pragma unroll
            for (int rr = 0; rr < 2; rr++) {
                int m = cRow * 128 + wm * 64 + i * 16 + g + rr * 8;
                int bwin = m / NTOK;
                int nn = m - bwin * NTOK;
                float* dst = gdst + (((size_t)(bwin * HEADS + h) * NTOK + nn) * HD);
                #pragma unroll
                for (int j = 0; j < 4; j++) {
                    float2 o;
                    o.x = (acc[i][j][rr * 2 + 0] + bv[j][0]) * sc;
                    o.y = (acc[i][j][rr * 2 + 1] + bv[j][1]) * sc;
                    *(float2*)(dst + j * 8 + 2 * q) = o;
                }
            }
        }
    } else {
        #pragma unroll
        for (int i = 0; i < 4; i++) {
            #pragma unroll
            for (int rr = 0; rr < 2; rr++) {
                int m = cRow * 128 + wm * 64 + i * 16 + g + rr * 8;
                float* dst = Cout + (size_t)m * CDIM + nbase;
                #pragma unroll
                for (int j = 0; j < 4; j++) {
                    float2 o;
                    o.x = acc[i][j][rr * 2 + 0] + bv[j][0];
                    o.y = acc[i][j][rr * 2 + 1] + bv[j][1];
                    *(float2*)(dst + j * 8 + 2 * q) = o;
                }
            }
        }
    }
}

// ---------------------------------------------------------------------------
// MMA flash attention: 64 threads per (window, head). Queries padded 49->64,
// keys 49->56. BM prefetched from L2 as bf16x2 before the QK mma.
// Output to g_y tf32-rounded AND k-permuted (proj's cp.async consumes it).
// smem: Q[64][36] | K[56][36] | Vt[32][60]; P[64][60] aliases Q+K region.
// ---------------------------------------------------------------------------
#define PITCH 36
#define QS_OFF  0
#define KS_OFF  2304
#define VTS_OFF 4320
#define SM_FLOATS 6240

__global__ __launch_bounds__(64) void attn_mma_kernel() {
    __shared__ float sm[SM_FLOATS];
    float* Qs  = sm + QS_OFF;    // [64][36]
    float* Ks  = sm + KS_OFF;    // [56][36]
    float* Vts = sm + VTS_OFF;   // [32][60]
    float* Ps  = sm;             // [64][60] aliases Q+K after sync

    const int blk = blockIdx.x;          // b*8 + h
    const int b = blk >> 3, h = blk & 7;
    const int tid = threadIdx.x, wid = tid >> 5, lid = tid & 31;
    const int g = lid >> 2, q = lid & 3;
    const int rbase = wid * 32;

    const size_t base4 = (size_t)blk * (NTOK * HD / 4);
    const float4* qg4 = ((const float4*)g_q) + base4;
    const float4* kg4 = ((const float4*)g_k) + base4;
    const float4* vg4 = ((const float4*)g_v) + base4;
    const float4 z4 = make_float4(0.f, 0.f, 0.f, 0.f);

    for (int t = tid; t < 512; t += 64) {
        int row = t >> 3, c = t & 7;
        *(float4*)(Qs + row * PITCH + c * 4) = (row < NTOK) ? qg4[t] : z4;
    }
    for (int t = tid; t < 448; t += 64) {
        int row = t >> 3, c = t & 7;
        float4 kv = (row < NTOK) ? kg4[t] : z4;
        *(float4*)(Ks + row * PITCH + c * 4) = kv;
        float4 vv = (row < NTOK) ? vg4[t] : z4;
        Vts[(c * 4 + 0) * 60 + row] = vv.x;
        Vts[(c * 4 + 1) * 60 + row] = vv.y;
        Vts[(c * 4 + 2) * 60 + row] = vv.z;
        Vts[(c * 4 + 3) * 60 + row] = vv.w;
    }
    __syncthreads();

    // ---- prefetch bias+mask (bf16x2) while QK mma runs ----
    const __nv_bfloat16* bmg = g_bm + ((size_t)((b & (NWIN - 1)) * HEADS + h)) * (64 * 56);
    uint32_t bmr[2][2][7];
    #pragma unroll
    for (int mi = 0; mi < 2; mi++) {
        const int r0 = rbase + mi * 16 + g;
        #pragma unroll
        for (int nj = 0; nj < 7; nj++) {
            const int cc = nj * 8 + 2 * q;
            bmr[mi][0][nj] = *(const uint32_t*)(bmg + r0 * 56 + cc);
            bmr[mi][1][nj] = *(const uint32_t*)(bmg + (r0 + 8) * 56 + cc);
        }
    }

    // ---- QK^T ----
    float s[2][7][4];
    #pragma unroll
    for (int mi = 0; mi < 2; mi++)
        #pragma unroll
        for (int nj = 0; nj < 7; nj++)
            #pragma unroll
            for (int r = 0; r < 4; r++) s[mi][nj][r] = 0.0f;

    #pragma unroll
    for (int ks = 0; ks < 4; ks++) {
        const int kc = ks * 8 + q;
        uint32_t b0[7], b1[7];
        #pragma unroll
        for (int nj = 0; nj < 7; nj++) {
            const float* bp = Ks + (nj * 8 + g) * PITCH + kc;
            b0[nj] = __float_as_uint(bp[0]);
            b1[nj] = __float_as_uint(bp[4]);
        }
        #pragma unroll
        for (int mi = 0; mi < 2; mi++) {
            const float* ap = Qs + (rbase + mi * 16 + g) * PITCH + kc;
            uint32_t a0 = __float_as_uint(ap[0]);
            uint32_t a2 = __float_as_uint(ap[4]);
            uint32_t a1 = __float_as_uint(ap[8 * PITCH]);
            uint32_t a3 = __float_as_uint(ap[8 * PITCH + 4]);
            #pragma unroll
            for (int nj = 0; nj < 7; nj++)
                MMA_TF32(s[mi][nj], a0, a1, a2, a3, b0[nj], b1[nj]);
        }
    }

    // ---- softmax ----
    float inv[2][2];
    #pragma unroll
    for (int mi = 0; mi < 2; mi++) {
        float l0 = 0.0f, l1 = 0.0f;
        #pragma unroll
        for (int nj = 0; nj < 7; nj++) {
            float2 bmA = __bfloat1622float2(*(__nv_bfloat162*)&bmr[mi][0][nj]);
            float2 bmB = __bfloat1622float2(*(__nv_bfloat162*)&bmr[mi][1][nj]);
            float e0 = __expf(s[mi][nj][0] + bmA.x);
            float e1 = __expf(s[mi][nj][1] + bmA.y);
            float e2 = __expf(s[mi][nj][2] + bmB.x);
            float e3 = __expf(s[mi][nj][3] + bmB.y);
            s[mi][nj][0] = e0; s[mi][nj][1] = e1;
            s[mi][nj][2] = e2; s[mi][nj][3] = e3;
            l0 += e0 + e1;
            l1 += e2 + e3;
        }
        l0 += __shfl_xor_sync(0xffffffffu, l0, 1);
        l0 += __shfl_xor_sync(0xffffffffu, l0, 2);
        l1 += __shfl_xor_sync(0xffffffffu, l1, 1);
        l1 += __shfl_xor_sync(0xffffffffu, l1, 2);
        inv[mi][0] = 1.0f / l0;
        inv[mi][1] = 1.0f / l1;
    }

    __syncthreads();   // both warps done reading Qs/Ks before P overwrites

    // ---- stage P ----
    #pragma unroll
    for (int mi = 0; mi < 2; mi++) {
        const int r0 = rbase + mi * 16 + g;
        #pragma unroll
        for (int nj = 0; nj < 7; nj++) {
            const int cc = nj * 8 + 2 * q;
            *(float2*)(Ps + r0 * 60 + cc)       = make_float2(s[mi][nj][0], s[mi][nj][1]);
            *(float2*)(Ps + (r0 + 8) * 60 + cc) = make_float2(s[mi][nj][2], s[mi][nj][3]);
        }
    }
    __syncwarp();

    // ---- P x V ----
    float o[2][4][4];
    #pragma unroll
    for (int mi = 0; mi < 2; mi++)
        #pragma unroll
        for (int nj = 0; nj < 4; nj++)
            #pragma unroll
            for (int r = 0; r < 4; r++) o[mi][nj][r] = 0.0f;

    #pragma unroll
    for (int ks = 0; ks < 7; ks++) {
        const int kc = ks * 8 + q;
        uint32_t b0[4], b1[4];
        #pragma unroll
        for (int nj = 0; nj < 4; nj++) {
            const float* bp = Vts + (nj * 8 + g) * 60 + kc;
            b0[nj] = __float_as_uint(bp[0]);
            b1[nj] = __float_as_uint(bp[4]);
        }
        #pragma unroll
        for (int mi = 0; mi < 2; mi++) {
            const float* ap = Ps + (rbase + mi * 16 + g) * 60 + kc;
            uint32_t a0 = __float_as_uint(ap[0]);
            uint32_t a2 = __float_as_uint(ap[4]);
            uint32_t a1 = __float_as_uint(ap[8 * 60]);
            uint32_t a3 = __float_as_uint(ap[8 * 60 + 4]);
            #pragma unroll
            for (int nj = 0; nj < 4; nj++)
                MMA_TF32(o[mi][nj], a0, a1, a2, a3, b0[nj], b1[nj]);
        }
    }

    // ---- normalize + store to g_y (tf32-rounded, k-permuted) ----
    const int p0 = ((q & 1) << 2) | (q >> 1);   // phys col of logical 2q; +2 for 2q+1
    #pragma unroll
    for (int mi = 0; mi < 2; mi++) {
        #pragma unroll
        for (int rr = 0; rr < 2; rr++) {
            const int row = rbase + mi * 16 + g + rr * 8;
            if (row < NTOK) {
                const float iv = inv[mi][rr];
                float* dst = g_y + ((size_t)b * NTOK + row) * CDIM + h * HD;
                #pragma unroll
                for (int nj = 0; nj < 4; nj++) {
                    dst[nj * 8 + p0]     = to_tf32(o[mi][nj][rr * 2 + 0] * iv);
                    dst[nj * 8 + p0 + 2] = to_tf32(o[mi][nj][rr * 2 + 1] * iv);
                }
            }
        }
    }
}

// ---------------------------------------------------------------------------
// Launch
// ---------------------------------------------------------------------------
extern "C" void kernel_launch(void* const* d_in, const int* in_sizes, int n_in,
                              void* d_out, int out_size)
{
    const float* x          = (const float*)d_in[0];
    const float* mask       = (const float*)d_in[1];
    const float* qkv_w      = (const float*)d_in[2];
    const float* qkv_b      = (const float*)d_in[3];
    const float* bias_table = (const float*)d_in[4];
    const float* proj_w     = (const float*)d_in[5];
    const float* proj_b     = (const float*)d_in[6];
    const int*   rel_idx    = (const int*)d_in[7];
    float* out = (float*)d_out;

    cudaFuncSetAttribute(tc_gemm<0>, cudaFuncAttributeMaxDynamicSharedMemorySize, SMTOT_BYTES);
    cudaFuncSetAttribute(tc_gemm<1>, cudaFuncAttributeMaxDynamicSharedMemorySize, SMTOT_BYTES);

    // 0) prepass: round+permute x; weight transposes (permuted); bf16 bias+mask
    round_x_kernel<<<M_TOTAL * CDIM / 4096, 256>>>(x);
    transpose_kernel<<<dim3(QKV_N / 32, CDIM / 32), dim3(32, 8)>>>(qkv_w, CDIM, QKV_N, 0);
    transpose_kernel<<<dim3(CDIM / 32, CDIM / 32), dim3(32, 8)>>>(proj_w, CDIM, CDIM, 1);
    bm_kernel<<<NWIN * HEADS, 256>>>(bias_table, mask, rel_idx);

    // 1) QKV: g_xr [200704 x 256] x [256 x 768] -> g_q/g_k/g_v
    tc_gemm<0><<<dim3(QKV_N / 128, M_TOTAL / 128), 256, SMTOT_BYTES>>>(qkv_b, nullptr);

    // 2) attention -> g_y (tf32-rounded, k-permuted)
    attn_mma_kernel<<<BATCH * HEADS, 64>>>();

    // 3) proj: g_y x [256 x 256] -> out
    tc_gemm<1><<<dim3(CDIM / 128, M_TOTAL / 128), 256, SMTOT_BYTES>>>(proj_b, out);
}